// round 1
// baseline (speedup 1.0000x reference)
#include <cuda_runtime.h>
#include <cstddef>

// Problem constants
#define B_  4
#define L_  1024
#define D_  512
#define H_  8
#define EK_ 64
#define KW_ 64          // local window
#define PADF 32         // K/2
#define M_  (B_ * L_)   // 4096 rows for projections

// ---------------------------------------------------------------------------
// Scratch (device globals -- no runtime allocation allowed)
// ---------------------------------------------------------------------------
__device__ float g_q[B_ * L_ * D_];
__device__ float g_k[B_ * L_ * D_];
__device__ float g_v[B_ * L_ * D_];
__device__ float g_attn[B_ * L_ * D_];

// ---------------------------------------------------------------------------
// SGEMM: C[M,N] = A[M,K] @ W[K,N], fp32, 128x128x8 tiles, 8x8 per thread.
// All dims divisible by tiles (M=4096, N=512, K=512). 256 threads.
// ---------------------------------------------------------------------------
__device__ __forceinline__ void sgemm_body(
    const float* __restrict__ A, const float* __restrict__ W,
    float* __restrict__ C, int M, int N, int K, int bx, int by)
{
    __shared__ float As[8][128];
    __shared__ float Bs[8][128];

    const int t  = threadIdx.x;
    const int tx = t & 15;          // 0..15 -> col group
    const int ty = t >> 4;          // 0..15 -> row group

    const float* Ab = A + (size_t)by * 128 * K;
    const float* Wb = W + (size_t)bx * 128;

    const int aRow = t >> 1;            // 0..127
    const int aCol = (t & 1) * 4;       // 0 or 4
    const int bRow = t >> 5;            // 0..7
    const int bCol = (t & 31) * 4;      // 0..124

    float acc[8][8];
    #pragma unroll
    for (int i = 0; i < 8; i++)
        #pragma unroll
        for (int j = 0; j < 8; j++) acc[i][j] = 0.f;

    for (int k0 = 0; k0 < K; k0 += 8) {
        float4 a4 = *(const float4*)(Ab + (size_t)aRow * K + k0 + aCol);
        As[aCol + 0][aRow] = a4.x;
        As[aCol + 1][aRow] = a4.y;
        As[aCol + 2][aRow] = a4.z;
        As[aCol + 3][aRow] = a4.w;
        float4 b4 = *(const float4*)(Wb + (size_t)(k0 + bRow) * N + bCol);
        *(float4*)&Bs[bRow][bCol] = b4;
        __syncthreads();

        #pragma unroll
        for (int kk = 0; kk < 8; kk++) {
            float am[8], bn[8];
            *(float4*)&am[0] = *(float4*)&As[kk][ty * 8];
            *(float4*)&am[4] = *(float4*)&As[kk][ty * 8 + 4];
            *(float4*)&bn[0] = *(float4*)&Bs[kk][tx * 8];
            *(float4*)&bn[4] = *(float4*)&Bs[kk][tx * 8 + 4];
            #pragma unroll
            for (int i = 0; i < 8; i++)
                #pragma unroll
                for (int j = 0; j < 8; j++)
                    acc[i][j] += am[i] * bn[j];
        }
        __syncthreads();
    }

    #pragma unroll
    for (int i = 0; i < 8; i++) {
        float* Crow = C + (size_t)(by * 128 + ty * 8 + i) * N + bx * 128 + tx * 8;
        *(float4*)Crow       = make_float4(acc[i][0], acc[i][1], acc[i][2], acc[i][3]);
        *(float4*)(Crow + 4) = make_float4(acc[i][4], acc[i][5], acc[i][6], acc[i][7]);
    }
}

// Fused QKV projections: blockIdx.z selects (input, weight, output) triple.
__global__ __launch_bounds__(256) void sgemm_qkv_kernel(
    const float* __restrict__ q_in, const float* __restrict__ k_in,
    const float* __restrict__ v_in,
    const float* __restrict__ Wq, const float* __restrict__ Wk,
    const float* __restrict__ Wv,
    float* __restrict__ q_out, float* __restrict__ k_out,
    float* __restrict__ v_out)
{
    const float* A;
    const float* W;
    float* C;
    if (blockIdx.z == 0)      { A = q_in; W = Wq; C = q_out; }
    else if (blockIdx.z == 1) { A = k_in; W = Wk; C = k_out; }
    else                      { A = v_in; W = Wv; C = v_out; }
    sgemm_body(A, W, C, M_, D_, D_, blockIdx.x, blockIdx.y);
}

__global__ __launch_bounds__(256) void sgemm_out_kernel(
    const float* __restrict__ A, const float* __restrict__ W,
    float* __restrict__ C)
{
    sgemm_body(A, W, C, M_, D_, D_, blockIdx.x, blockIdx.y);
}

// ---------------------------------------------------------------------------
// Local attention.
// Grid: (L/64, H, B). Block: 256 threads = 64 query rows x 4 lanes.
// smem (dynamic, padded stride 68 floats): sQ[64], sK[128], sV[128] rows.
// scores[l][k] = q[l] . key[l + k - 32]   (k in [0,64), OOB masked -inf)
// ---------------------------------------------------------------------------
#define ROWSTR 68
#define SMEM_FLOATS ((64 + 128 + 128) * ROWSTR)

__global__ __launch_bounds__(256) void local_attn_kernel(
    const float* __restrict__ Q, const float* __restrict__ Kp,
    const float* __restrict__ Vp, const unsigned char* __restrict__ mask,
    float* __restrict__ Out)
{
    extern __shared__ float sm[];
    float* sQ = sm;
    float* sK = sm + 64 * ROWSTR;
    float* sV = sK + 128 * ROWSTR;

    const int l0 = blockIdx.x * 64;
    const int h  = blockIdx.y;
    const int b  = blockIdx.z;
    const int t  = threadIdx.x;

    const size_t headoff = (size_t)h * EK_;
    const float* Qbase = Q  + (size_t)b * L_ * D_ + headoff;
    const float* Kbase = Kp + (size_t)b * L_ * D_ + headoff;
    const float* Vbase = Vp + (size_t)b * L_ * D_ + headoff;

    // Load Q tile: 64 rows x 16 float4
    for (int i = t; i < 64 * 16; i += 256) {
        int row = i >> 4, c4 = i & 15;
        float4 v = *(const float4*)(Qbase + (size_t)(l0 + row) * D_ + c4 * 4);
        *(float4*)&sQ[row * ROWSTR + c4 * 4] = v;
    }
    // Load K/V window: rows j=0..127, global index gl = l0 - 32 + j
    for (int i = t; i < 128 * 16; i += 256) {
        int row = i >> 4, c4 = i & 15;
        int gl = l0 - PADF + row;
        float4 kv, vv;
        if (gl >= 0 && gl < L_) {
            kv = *(const float4*)(Kbase + (size_t)gl * D_ + c4 * 4);
            vv = *(const float4*)(Vbase + (size_t)gl * D_ + c4 * 4);
        } else {
            kv = make_float4(0.f, 0.f, 0.f, 0.f);
            vv = kv;
        }
        *(float4*)&sK[row * ROWSTR + c4 * 4] = kv;
        *(float4*)&sV[row * ROWSTR + c4 * 4] = vv;
    }
    __syncthreads();

    const int g     = t >> 2;   // query row in tile (0..63)
    const int lane4 = t & 3;    // k-chunk owner (0..3)
    const int l     = l0 + g;

    // ---- scores: lane owns k in [lane4*16, lane4*16+16) ----
    float s[16];
    #pragma unroll
    for (int kk = 0; kk < 16; kk++) s[kk] = 0.f;

    #pragma unroll
    for (int e4 = 0; e4 < 16; e4++) {
        float4 q4 = *(float4*)&sQ[g * ROWSTR + e4 * 4];
        #pragma unroll
        for (int kk = 0; kk < 16; kk++) {
            int j = g + lane4 * 16 + kk;   // window row = (l-l0) + k
            float4 k4 = *(float4*)&sK[j * ROWSTR + e4 * 4];
            s[kk] += q4.x * k4.x + q4.y * k4.y + q4.z * k4.z + q4.w * k4.w;
        }
    }

    // ---- mask (OOB window + key_padding_mask) ----
    const unsigned char* mrow = mask + (size_t)b * L_;
    #pragma unroll
    for (int kk = 0; kk < 16; kk++) {
        int k  = lane4 * 16 + kk;
        int gl = l + k - PADF;
        bool valid = (gl >= 0) && (gl < L_) && (mrow[gl] == 0);
        if (!valid) s[kk] = -1e30f;
    }

    // ---- softmax across the quad ----
    float m = s[0];
    #pragma unroll
    for (int kk = 1; kk < 16; kk++) m = fmaxf(m, s[kk]);
    m = fmaxf(m, __shfl_xor_sync(0xffffffffu, m, 1));
    m = fmaxf(m, __shfl_xor_sync(0xffffffffu, m, 2));
    float sum = 0.f;
    #pragma unroll
    for (int kk = 0; kk < 16; kk++) { s[kk] = expf(s[kk] - m); sum += s[kk]; }
    sum += __shfl_xor_sync(0xffffffffu, sum, 1);
    sum += __shfl_xor_sync(0xffffffffu, sum, 2);
    float inv = 1.f / sum;
    #pragma unroll
    for (int kk = 0; kk < 16; kk++) s[kk] *= inv;

    // ---- AV: lane owns dims [lane4*16, lane4*16+16) ----
    float acc[16];
    #pragma unroll
    for (int c = 0; c < 16; c++) acc[c] = 0.f;

    #pragma unroll
    for (int o = 0; o < 4; o++) {
        #pragma unroll
        for (int kk = 0; kk < 16; kk++) {
            float w = __shfl_sync(0xffffffffu, s[kk], o, 4);
            int j = g + o * 16 + kk;
            const float* vrow = &sV[j * ROWSTR + lane4 * 16];
            #pragma unroll
            for (int c4 = 0; c4 < 4; c4++) {
                float4 v4 = *(const float4*)&vrow[c4 * 4];
                acc[c4 * 4 + 0] += w * v4.x;
                acc[c4 * 4 + 1] += w * v4.y;
                acc[c4 * 4 + 2] += w * v4.z;
                acc[c4 * 4 + 3] += w * v4.w;
            }
        }
    }

    float* orow = Out + ((size_t)b * L_ + l) * D_ + headoff + lane4 * 16;
    #pragma unroll
    for (int c4 = 0; c4 < 4; c4++)
        *(float4*)&orow[c4 * 4] = make_float4(acc[c4 * 4 + 0], acc[c4 * 4 + 1],
                                              acc[c4 * 4 + 2], acc[c4 * 4 + 3]);
}

// ---------------------------------------------------------------------------
// Launch
// ---------------------------------------------------------------------------
extern "C" void kernel_launch(void* const* d_in, const int* in_sizes, int n_in,
                              void* d_out, int out_size)
{
    const float* query = (const float*)d_in[0];
    const float* key   = (const float*)d_in[1];
    const float* value = (const float*)d_in[2];
    const unsigned char* mask = (const unsigned char*)d_in[3];
    // d_in[4] = 'other' scalar, unused
    const float* Wq = (const float*)d_in[5];
    const float* Wk = (const float*)d_in[6];
    const float* Wv = (const float*)d_in[7];
    const float* Wo = (const float*)d_in[8];
    float* out = (float*)d_out;

    float *dq, *dk, *dv, *da;
    cudaGetSymbolAddress((void**)&dq, g_q);
    cudaGetSymbolAddress((void**)&dk, g_k);
    cudaGetSymbolAddress((void**)&dv, g_v);
    cudaGetSymbolAddress((void**)&da, g_attn);

    // 1) QKV projections (3 GEMMs in one launch)
    dim3 gqkv(D_ / 128, M_ / 128, 3);   // (4, 32, 3)
    sgemm_qkv_kernel<<<gqkv, 256>>>(query, key, value, Wq, Wk, Wv, dq, dk, dv);

    // 2) local attention
    const int smem_bytes = SMEM_FLOATS * sizeof(float);  // ~85 KB
    cudaFuncSetAttribute(local_attn_kernel,
                         cudaFuncAttributeMaxDynamicSharedMemorySize, smem_bytes);
    dim3 gattn(L_ / 64, H_, B_);        // (16, 8, 4)
    local_attn_kernel<<<gattn, 256, smem_bytes>>>(dq, dk, dv, mask, da);

    // 3) output projection
    dim3 gout(D_ / 128, M_ / 128);      // (4, 32)
    sgemm_out_kernel<<<gout, 256>>>(da, Wo, out);
}

// round 5
// speedup vs baseline: 1.3281x; 1.3281x over previous
#include <cuda_runtime.h>
#include <cuda_bf16.h>
#include <mma.h>
#include <cstdint>
#include <cstddef>

using namespace nvcuda;

// Problem constants
#define B_   4
#define L_   1024
#define D_   512
#define H_   8
#define EK_  64
#define PADF 32
#define M_   (B_ * L_)    // 4096
#define K2_  1536         // K tripled: [hi|hi|lo] x [hi|lo|hi] compensated layout

// ---------------------------------------------------------------------------
// Scratch (device globals -- no runtime allocation allowed)
// ---------------------------------------------------------------------------
__device__ float g_q[M_ * D_];
__device__ float g_k[M_ * D_];
__device__ float g_v[M_ * D_];
__device__ float g_attn[M_ * D_];
__device__ __align__(256) __nv_bfloat16 g_in2[3ull * M_ * K2_];  // split q,k,v
__device__ __align__(256) __nv_bfloat16 g_attn2[(size_t)M_ * K2_];
__device__ __align__(256) __nv_bfloat16 g_w2[4ull * D_ * K2_];   // split+T weights

// ---------------------------------------------------------------------------
// 2-way split: x = hi + lo (bf16 each).
// A-side layout: [hi | hi | lo];  W-side layout: [hi | lo | hi]
// so the single long-K GEMM computes a_hi*w_hi + a_hi*w_lo + a_lo*w_hi.
// Missing a_lo*w_lo ~ 2^-18 relative -> well under threshold.
// ---------------------------------------------------------------------------
__device__ __forceinline__ void split2(float x, __nv_bfloat16& hi,
                                       __nv_bfloat16& lo)
{
    hi = __float2bfloat16(x);
    lo = __float2bfloat16(x - __bfloat162float(hi));
}

__global__ __launch_bounds__(256) void split_in_kernel(
    const float* __restrict__ q, const float* __restrict__ k,
    const float* __restrict__ v)
{
    int i = blockIdx.x * 256 + threadIdx.x;           // over M_*D_
    int s = blockIdx.y;
    const float* S = (s == 0) ? q : (s == 1) ? k : v;
    float x = S[i];
    __nv_bfloat16 hi, lo;
    split2(x, hi, lo);
    int r = i >> 9, c = i & 511;
    __nv_bfloat16* dst = g_in2 + (size_t)s * M_ * K2_ + (size_t)r * K2_;
    dst[c]        = hi;   // pairs with w_hi
    dst[512 + c]  = hi;   // pairs with w_lo
    dst[1024 + c] = lo;   // pairs with w_hi
}

__global__ __launch_bounds__(256) void split_attn_kernel()
{
    int i = blockIdx.x * 256 + threadIdx.x;
    float x = g_attn[i];
    __nv_bfloat16 hi, lo;
    split2(x, hi, lo);
    int r = i >> 9, c = i & 511;
    __nv_bfloat16* dst = g_attn2 + (size_t)r * K2_;
    dst[c]        = hi;
    dst[512 + c]  = hi;
    dst[1024 + c] = lo;
}

// Weights: W[K=512][N=512] row-major -> Wt[n][j]=hi, Wt[n][512+j]=lo, [1024+j]=hi
__global__ __launch_bounds__(256) void split_w_kernel(
    const float* __restrict__ Wq, const float* __restrict__ Wk,
    const float* __restrict__ Wv, const float* __restrict__ Wo)
{
    __shared__ float tile[64][65];
    int z = blockIdx.z;
    const float* W = (z == 0) ? Wq : (z == 1) ? Wk : (z == 2) ? Wv : Wo;
    int j0 = blockIdx.x * 64, n0 = blockIdx.y * 64;
    for (int i = threadIdx.x; i < 4096; i += 256) {
        int r = i >> 6, c = i & 63;
        tile[r][c] = W[(size_t)(j0 + r) * D_ + n0 + c];
    }
    __syncthreads();
    __nv_bfloat16* dst = g_w2 + (size_t)z * D_ * K2_;
    for (int i = threadIdx.x; i < 4096; i += 256) {
        int r = i >> 6, c = i & 63;           // r: local n, c: local j
        float x = tile[c][r];
        __nv_bfloat16 hi, lo;
        split2(x, hi, lo);
        __nv_bfloat16* row = dst + (size_t)(n0 + r) * K2_;
        row[j0 + c]        = hi;   // pairs with a_hi
        row[512 + j0 + c]  = lo;   // pairs with a_hi
        row[1024 + j0 + c] = hi;   // pairs with a_lo
    }
}

// ---------------------------------------------------------------------------
// wmma bf16 GEMM: C[M_,512] = A2[M_,1536] @ Wt[512,1536]^T
// Block tile 128x128, 8 warps (warp tile 64x32), K-chunk 32, 2-stage cp.async.
// ---------------------------------------------------------------------------
#define BM 128
#define BN 128
#define BK 32
#define STR 40                       // smem row stride (bf16 elems), 80B
#define NKT (K2_ / BK)               // 48
#define TILE_ELEMS (128 * STR)

__device__ __forceinline__ void cp16(uint32_t dst, const void* src) {
    asm volatile("cp.async.cg.shared.global [%0], [%1], 16;"
                 :: "r"(dst), "l"(src));
}

__device__ __forceinline__ uint32_t smem_u32(const void* p) {
    uint32_t a;
    asm("{ .reg .u64 t; cvta.to.shared.u64 t, %1; cvt.u32.u64 %0, t; }"
        : "=r"(a) : "l"(p));
    return a;
}

// Load one 128x32 bf16 tile (row-major, rows K2_-strided) into smem stage.
__device__ __forceinline__ void tile_loads(const __nv_bfloat16* __restrict__ G,
                                           uint32_t sbase, int t)
{
    #pragma unroll
    for (int i = 0; i < 2; i++) {
        int idx = t + i * 256;              // 0..511 chunks of 16B
        int row = idx >> 2, c = idx & 3;
        cp16(sbase + (uint32_t)(row * (STR * 2) + c * 16),
             G + (size_t)row * K2_ + c * 8);
    }
}

__global__ __launch_bounds__(256) void gemm3_kernel(
    const __nv_bfloat16* __restrict__ A0, const __nv_bfloat16* __restrict__ A1,
    const __nv_bfloat16* __restrict__ A2,
    const __nv_bfloat16* __restrict__ Bw0, const __nv_bfloat16* __restrict__ Bw1,
    const __nv_bfloat16* __restrict__ Bw2,
    float* __restrict__ C0, float* __restrict__ C1, float* __restrict__ C2)
{
    __shared__ __nv_bfloat16 sA[2][TILE_ELEMS];
    __shared__ __nv_bfloat16 sB[2][TILE_ELEMS];

    const int z = blockIdx.z;
    const __nv_bfloat16* A  = (z == 0) ? A0  : (z == 1) ? A1  : A2;
    const __nv_bfloat16* Bw = (z == 0) ? Bw0 : (z == 1) ? Bw1 : Bw2;
    float* C                = (z == 0) ? C0  : (z == 1) ? C1  : C2;

    const int t   = threadIdx.x;
    const int wid = t >> 5;
    const int wm  = wid & 1;       // 2 m-groups of 64
    const int wn  = wid >> 1;      // 4 n-groups of 32
    const int m0  = blockIdx.y * BM, n0 = blockIdx.x * BN;

    const __nv_bfloat16* Abase = A  + (size_t)m0 * K2_;
    const __nv_bfloat16* Bbase = Bw + (size_t)n0 * K2_;
    const uint32_t sAb = smem_u32(sA), sBb = smem_u32(sB);
    const uint32_t stage_bytes = TILE_ELEMS * 2;

    wmma::fragment<wmma::accumulator, 16, 16, 16, float> cf[4][2];
    #pragma unroll
    for (int i = 0; i < 4; i++)
        #pragma unroll
        for (int j = 0; j < 2; j++) wmma::fill_fragment(cf[i][j], 0.f);

    tile_loads(Abase, sAb, t);
    tile_loads(Bbase, sBb, t);
    asm volatile("cp.async.commit_group;");

    #pragma unroll 1
    for (int kt = 0; kt < NKT; kt++) {
        const int s = kt & 1;
        if (kt + 1 < NKT) {
            const int so = s ^ 1;
            tile_loads(Abase + (kt + 1) * BK, sAb + so * stage_bytes, t);
            tile_loads(Bbase + (kt + 1) * BK, sBb + so * stage_bytes, t);
            asm volatile("cp.async.commit_group;");
            asm volatile("cp.async.wait_group 1;");
        } else {
            asm volatile("cp.async.wait_group 0;");
        }
        __syncthreads();

        const __nv_bfloat16* sa = sA[s];
        const __nv_bfloat16* sb = sB[s];
        #pragma unroll
        for (int kk = 0; kk < BK; kk += 16) {
            wmma::fragment<wmma::matrix_a, 16, 16, 16, __nv_bfloat16,
                           wmma::row_major> af[4];
            wmma::fragment<wmma::matrix_b, 16, 16, 16, __nv_bfloat16,
                           wmma::col_major> bf[2];
            #pragma unroll
            for (int i = 0; i < 4; i++)
                wmma::load_matrix_sync(af[i],
                    sa + (wm * 64 + i * 16) * STR + kk, STR);
            #pragma unroll
            for (int j = 0; j < 2; j++)
                wmma::load_matrix_sync(bf[j],
                    sb + (wn * 32 + j * 16) * STR + kk, STR);
            #pragma unroll
            for (int i = 0; i < 4; i++)
                #pragma unroll
                for (int j = 0; j < 2; j++)
                    wmma::mma_sync(cf[i][j], af[i], bf[j], cf[i][j]);
        }
        __syncthreads();
    }

    #pragma unroll
    for (int i = 0; i < 4; i++)
        #pragma unroll
        for (int j = 0; j < 2; j++)
            wmma::store_matrix_sync(
                C + (size_t)(m0 + wm * 64 + i * 16) * D_ + n0 + wn * 32 + j * 16,
                cf[i][j], D_, wmma::mem_row_major);
}

// ---------------------------------------------------------------------------
// Local attention (unchanged, known correct).
// ---------------------------------------------------------------------------
#define ROWSTR 68
#define SMEM_FLOATS ((64 + 128 + 128) * ROWSTR)

__global__ __launch_bounds__(256) void local_attn_kernel(
    const float* __restrict__ Q, const float* __restrict__ Kp,
    const float* __restrict__ Vp, const unsigned char* __restrict__ mask,
    float* __restrict__ Out)
{
    extern __shared__ float smf[];
    float* sQ = smf;
    float* sK = smf + 64 * ROWSTR;
    float* sV = sK + 128 * ROWSTR;

    const int l0 = blockIdx.x * 64;
    const int h  = blockIdx.y;
    const int b  = blockIdx.z;
    const int t  = threadIdx.x;

    const size_t headoff = (size_t)h * EK_;
    const float* Qbase = Q  + (size_t)b * L_ * D_ + headoff;
    const float* Kbase = Kp + (size_t)b * L_ * D_ + headoff;
    const float* Vbase = Vp + (size_t)b * L_ * D_ + headoff;

    for (int i = t; i < 64 * 16; i += 256) {
        int row = i >> 4, c4 = i & 15;
        float4 v = *(const float4*)(Qbase + (size_t)(l0 + row) * D_ + c4 * 4);
        *(float4*)&sQ[row * ROWSTR + c4 * 4] = v;
    }
    for (int i = t; i < 128 * 16; i += 256) {
        int row = i >> 4, c4 = i & 15;
        int gl = l0 - PADF + row;
        float4 kv, vv;
        if (gl >= 0 && gl < L_) {
            kv = *(const float4*)(Kbase + (size_t)gl * D_ + c4 * 4);
            vv = *(const float4*)(Vbase + (size_t)gl * D_ + c4 * 4);
        } else {
            kv = make_float4(0.f, 0.f, 0.f, 0.f);
            vv = kv;
        }
        *(float4*)&sK[row * ROWSTR + c4 * 4] = kv;
        *(float4*)&sV[row * ROWSTR + c4 * 4] = vv;
    }
    __syncthreads();

    const int g     = t >> 2;
    const int lane4 = t & 3;
    const int l     = l0 + g;

    float s[16];
    #pragma unroll
    for (int kk = 0; kk < 16; kk++) s[kk] = 0.f;

    #pragma unroll
    for (int e4 = 0; e4 < 16; e4++) {
        float4 q4 = *(float4*)&sQ[g * ROWSTR + e4 * 4];
        #pragma unroll
        for (int kk = 0; kk < 16; kk++) {
            int j = g + lane4 * 16 + kk;
            float4 k4 = *(float4*)&sK[j * ROWSTR + e4 * 4];
            s[kk] += q4.x * k4.x + q4.y * k4.y + q4.z * k4.z + q4.w * k4.w;
        }
    }

    const unsigned char* mrow = mask + (size_t)b * L_;
    #pragma unroll
    for (int kk = 0; kk < 16; kk++) {
        int k  = lane4 * 16 + kk;
        int gl = l + k - PADF;
        bool valid = (gl >= 0) && (gl < L_) && (mrow[gl] == 0);
        if (!valid) s[kk] = -1e30f;
    }

    float m = s[0];
    #pragma unroll
    for (int kk = 1; kk < 16; kk++) m = fmaxf(m, s[kk]);
    m = fmaxf(m, __shfl_xor_sync(0xffffffffu, m, 1));
    m = fmaxf(m, __shfl_xor_sync(0xffffffffu, m, 2));
    float sum = 0.f;
    #pragma unroll
    for (int kk = 0; kk < 16; kk++) { s[kk] = expf(s[kk] - m); sum += s[kk]; }
    sum += __shfl_xor_sync(0xffffffffu, sum, 1);
    sum += __shfl_xor_sync(0xffffffffu, sum, 2);
    float inv = 1.f / sum;
    #pragma unroll
    for (int kk = 0; kk < 16; kk++) s[kk] *= inv;

    float acc[16];
    #pragma unroll
    for (int c = 0; c < 16; c++) acc[c] = 0.f;

    #pragma unroll
    for (int o = 0; o < 4; o++) {
        #pragma unroll
        for (int kk = 0; kk < 16; kk++) {
            float w = __shfl_sync(0xffffffffu, s[kk], o, 4);
            int j = g + o * 16 + kk;
            const float* vrow = &sV[j * ROWSTR + lane4 * 16];
            #pragma unroll
            for (int c4 = 0; c4 < 4; c4++) {
                float4 v4 = *(const float4*)&vrow[c4 * 4];
                acc[c4 * 4 + 0] += w * v4.x;
                acc[c4 * 4 + 1] += w * v4.y;
                acc[c4 * 4 + 2] += w * v4.z;
                acc[c4 * 4 + 3] += w * v4.w;
            }
        }
    }

    float* orow = Out + ((size_t)b * L_ + l) * D_ + headoff + lane4 * 16;
    #pragma unroll
    for (int c4 = 0; c4 < 4; c4++)
        *(float4*)&orow[c4 * 4] = make_float4(acc[c4 * 4 + 0], acc[c4 * 4 + 1],
                                              acc[c4 * 4 + 2], acc[c4 * 4 + 3]);
}

// ---------------------------------------------------------------------------
// Launch
// ---------------------------------------------------------------------------
extern "C" void kernel_launch(void* const* d_in, const int* in_sizes, int n_in,
                              void* d_out, int out_size)
{
    const float* query = (const float*)d_in[0];
    const float* key   = (const float*)d_in[1];
    const float* value = (const float*)d_in[2];
    const unsigned char* mask = (const unsigned char*)d_in[3];
    const float* Wq = (const float*)d_in[5];
    const float* Wk = (const float*)d_in[6];
    const float* Wv = (const float*)d_in[7];
    const float* Wo = (const float*)d_in[8];
    float* out = (float*)d_out;

    float *dq, *dk, *dv, *da;
    __nv_bfloat16 *din2, *dat2, *dw2;
    cudaGetSymbolAddress((void**)&dq, g_q);
    cudaGetSymbolAddress((void**)&dk, g_k);
    cudaGetSymbolAddress((void**)&dv, g_v);
    cudaGetSymbolAddress((void**)&da, g_attn);
    cudaGetSymbolAddress((void**)&din2, g_in2);
    cudaGetSymbolAddress((void**)&dat2, g_attn2);
    cudaGetSymbolAddress((void**)&dw2, g_w2);

    const int attn_smem = SMEM_FLOATS * sizeof(float);
    cudaFuncSetAttribute(local_attn_kernel,
                         cudaFuncAttributeMaxDynamicSharedMemorySize, attn_smem);

    // 1) split inputs + weights into compensated bf16 layouts
    split_in_kernel<<<dim3(M_ * D_ / 256, 3), 256>>>(query, key, value);
    split_w_kernel<<<dim3(8, 8, 4), 256>>>(Wq, Wk, Wv, Wo);

    // 2) QKV projections: 3 GEMMs in one tensor-core launch
    const __nv_bfloat16* Aq = din2;
    const __nv_bfloat16* Ak = din2 + (size_t)1 * M_ * K2_;
    const __nv_bfloat16* Av = din2 + (size_t)2 * M_ * K2_;
    const __nv_bfloat16* Bq = dw2;
    const __nv_bfloat16* Bk = dw2 + (size_t)1 * D_ * K2_;
    const __nv_bfloat16* Bv = dw2 + (size_t)2 * D_ * K2_;
    const __nv_bfloat16* Bo = dw2 + (size_t)3 * D_ * K2_;
    gemm3_kernel<<<dim3(D_ / BN, M_ / BM, 3), 256>>>(Aq, Ak, Av, Bq, Bk, Bv,
                                                     dq, dk, dv);

    // 3) local attention (fp32)
    local_attn_kernel<<<dim3(16, 8, 4), 256, attn_smem>>>(dq, dk, dv, mask, da);

    // 4) split attention output, then output projection
    split_attn_kernel<<<M_ * D_ / 256, 256>>>();
    gemm3_kernel<<<dim3(D_ / BN, M_ / BM, 1), 256>>>(dat2, dat2, dat2,
                                                     Bo, Bo, Bo, out, out, out);
}

// round 6
// speedup vs baseline: 1.6063x; 1.2095x over previous
#include <cuda_runtime.h>
#include <cuda_bf16.h>
#include <mma.h>
#include <cstdint>
#include <cstddef>

using namespace nvcuda;

// Problem constants
#define B_   4
#define L_   1024
#define D_   512
#define H_   8
#define EK_  64
#define PADF 32
#define M_   (B_ * L_)    // 4096
#define K2_  1536         // K tripled: [hi|hi|lo] x [hi|lo|hi] compensated layout

// ---------------------------------------------------------------------------
// Scratch (device globals -- no runtime allocation allowed)
// ---------------------------------------------------------------------------
__device__ float g_q[M_ * D_];
__device__ float g_k[M_ * D_];
__device__ float g_v[M_ * D_];
__device__ float g_attn[M_ * D_];
__device__ __align__(256) __nv_bfloat16 g_in2[3ull * M_ * K2_];  // split q,k,v
__device__ __align__(256) __nv_bfloat16 g_attn2[(size_t)M_ * K2_];
__device__ __align__(256) __nv_bfloat16 g_w2[4ull * D_ * K2_];   // split+T weights

// ---------------------------------------------------------------------------
// 2-way split: x = hi + lo (bf16 each).
// ---------------------------------------------------------------------------
__device__ __forceinline__ void split2(float x, __nv_bfloat16& hi,
                                       __nv_bfloat16& lo)
{
    hi = __float2bfloat16(x);
    lo = __float2bfloat16(x - __bfloat162float(hi));
}

__global__ __launch_bounds__(256) void split_in_kernel(
    const float* __restrict__ q, const float* __restrict__ k,
    const float* __restrict__ v)
{
    int i = blockIdx.x * 256 + threadIdx.x;           // over M_*D_
    int s = blockIdx.y;
    const float* S = (s == 0) ? q : (s == 1) ? k : v;
    float x = S[i];
    __nv_bfloat16 hi, lo;
    split2(x, hi, lo);
    int r = i >> 9, c = i & 511;
    __nv_bfloat16* dst = g_in2 + (size_t)s * M_ * K2_ + (size_t)r * K2_;
    dst[c]        = hi;   // pairs with w_hi
    dst[512 + c]  = hi;   // pairs with w_lo
    dst[1024 + c] = lo;   // pairs with w_hi
}

__global__ __launch_bounds__(256) void split_attn_kernel()
{
    int i = blockIdx.x * 256 + threadIdx.x;
    float x = g_attn[i];
    __nv_bfloat16 hi, lo;
    split2(x, hi, lo);
    int r = i >> 9, c = i & 511;
    __nv_bfloat16* dst = g_attn2 + (size_t)r * K2_;
    dst[c]        = hi;
    dst[512 + c]  = hi;
    dst[1024 + c] = lo;
}

// Weights: W[K=512][N=512] row-major -> Wt[n][j]=hi, Wt[n][512+j]=lo, [1024+j]=hi
__global__ __launch_bounds__(256) void split_w_kernel(
    const float* __restrict__ Wq, const float* __restrict__ Wk,
    const float* __restrict__ Wv, const float* __restrict__ Wo)
{
    __shared__ float tile[64][65];
    int z = blockIdx.z;
    const float* W = (z == 0) ? Wq : (z == 1) ? Wk : (z == 2) ? Wv : Wo;
    int j0 = blockIdx.x * 64, n0 = blockIdx.y * 64;
    for (int i = threadIdx.x; i < 4096; i += 256) {
        int r = i >> 6, c = i & 63;
        tile[r][c] = W[(size_t)(j0 + r) * D_ + n0 + c];
    }
    __syncthreads();
    __nv_bfloat16* dst = g_w2 + (size_t)z * D_ * K2_;
    for (int i = threadIdx.x; i < 4096; i += 256) {
        int r = i >> 6, c = i & 63;           // r: local n, c: local j
        float x = tile[c][r];
        __nv_bfloat16 hi, lo;
        split2(x, hi, lo);
        __nv_bfloat16* row = dst + (size_t)(n0 + r) * K2_;
        row[j0 + c]        = hi;
        row[512 + j0 + c]  = lo;
        row[1024 + j0 + c] = hi;
    }
}

// ---------------------------------------------------------------------------
// wmma bf16 GEMM: C[M_,512] = A2[M_,1536] @ Wt[512,1536]^T  (unchanged)
// ---------------------------------------------------------------------------
#define BM 128
#define BN 128
#define BK 32
#define STR 40
#define NKT (K2_ / BK)
#define TILE_ELEMS (128 * STR)

__device__ __forceinline__ void cp16(uint32_t dst, const void* src) {
    asm volatile("cp.async.cg.shared.global [%0], [%1], 16;"
                 :: "r"(dst), "l"(src));
}

__device__ __forceinline__ uint32_t smem_u32(const void* p) {
    uint32_t a;
    asm("{ .reg .u64 t; cvta.to.shared.u64 t, %1; cvt.u32.u64 %0, t; }"
        : "=r"(a) : "l"(p));
    return a;
}

__device__ __forceinline__ void tile_loads(const __nv_bfloat16* __restrict__ G,
                                           uint32_t sbase, int t)
{
    #pragma unroll
    for (int i = 0; i < 2; i++) {
        int idx = t + i * 256;
        int row = idx >> 2, c = idx & 3;
        cp16(sbase + (uint32_t)(row * (STR * 2) + c * 16),
             G + (size_t)row * K2_ + c * 8);
    }
}

__global__ __launch_bounds__(256) void gemm3_kernel(
    const __nv_bfloat16* __restrict__ A0, const __nv_bfloat16* __restrict__ A1,
    const __nv_bfloat16* __restrict__ A2,
    const __nv_bfloat16* __restrict__ Bw0, const __nv_bfloat16* __restrict__ Bw1,
    const __nv_bfloat16* __restrict__ Bw2,
    float* __restrict__ C0, float* __restrict__ C1, float* __restrict__ C2)
{
    __shared__ __nv_bfloat16 sA[2][TILE_ELEMS];
    __shared__ __nv_bfloat16 sB[2][TILE_ELEMS];

    const int z = blockIdx.z;
    const __nv_bfloat16* A  = (z == 0) ? A0  : (z == 1) ? A1  : A2;
    const __nv_bfloat16* Bw = (z == 0) ? Bw0 : (z == 1) ? Bw1 : Bw2;
    float* C                = (z == 0) ? C0  : (z == 1) ? C1  : C2;

    const int t   = threadIdx.x;
    const int wid = t >> 5;
    const int wm  = wid & 1;
    const int wn  = wid >> 1;
    const int m0  = blockIdx.y * BM, n0 = blockIdx.x * BN;

    const __nv_bfloat16* Abase = A  + (size_t)m0 * K2_;
    const __nv_bfloat16* Bbase = Bw + (size_t)n0 * K2_;
    const uint32_t sAb = smem_u32(sA), sBb = smem_u32(sB);
    const uint32_t stage_bytes = TILE_ELEMS * 2;

    wmma::fragment<wmma::accumulator, 16, 16, 16, float> cf[4][2];
    #pragma unroll
    for (int i = 0; i < 4; i++)
        #pragma unroll
        for (int j = 0; j < 2; j++) wmma::fill_fragment(cf[i][j], 0.f);

    tile_loads(Abase, sAb, t);
    tile_loads(Bbase, sBb, t);
    asm volatile("cp.async.commit_group;");

    #pragma unroll 1
    for (int kt = 0; kt < NKT; kt++) {
        const int s = kt & 1;
        if (kt + 1 < NKT) {
            const int so = s ^ 1;
            tile_loads(Abase + (kt + 1) * BK, sAb + so * stage_bytes, t);
            tile_loads(Bbase + (kt + 1) * BK, sBb + so * stage_bytes, t);
            asm volatile("cp.async.commit_group;");
            asm volatile("cp.async.wait_group 1;");
        } else {
            asm volatile("cp.async.wait_group 0;");
        }
        __syncthreads();

        const __nv_bfloat16* sa = sA[s];
        const __nv_bfloat16* sb = sB[s];
        #pragma unroll
        for (int kk = 0; kk < BK; kk += 16) {
            wmma::fragment<wmma::matrix_a, 16, 16, 16, __nv_bfloat16,
                           wmma::row_major> af[4];
            wmma::fragment<wmma::matrix_b, 16, 16, 16, __nv_bfloat16,
                           wmma::col_major> bf[2];
            #pragma unroll
            for (int i = 0; i < 4; i++)
                wmma::load_matrix_sync(af[i],
                    sa + (wm * 64 + i * 16) * STR + kk, STR);
            #pragma unroll
            for (int j = 0; j < 2; j++)
                wmma::load_matrix_sync(bf[j],
                    sb + (wn * 32 + j * 16) * STR + kk, STR);
            #pragma unroll
            for (int i = 0; i < 4; i++)
                #pragma unroll
                for (int j = 0; j < 2; j++)
                    wmma::mma_sync(cf[i][j], af[i], bf[j], cf[i][j]);
        }
        __syncthreads();
    }

    #pragma unroll
    for (int i = 0; i < 4; i++)
        #pragma unroll
        for (int j = 0; j < 2; j++)
            wmma::store_matrix_sync(
                C + (size_t)(m0 + wm * 64 + i * 16) * D_ + n0 + wn * 32 + j * 16,
                cf[i][j], D_, wmma::mem_row_major);
}

// ---------------------------------------------------------------------------
// wmma local attention. Grid (16, 8, 4), 256 threads.
//   S[64x128]  = Q2[64x192] @ K2[128x192]^T   (compensated bf16 split)
//   softmax over band (k = j-g in [0,64))
//   O[64x64]   = P2[64x384] @ V2[384x64]      (compensated split)
// ---------------------------------------------------------------------------
#define QLD 200     // bf16 ld for Q2/K2 (192 cols + pad)
#define SLD 132     // fp32 ld for S (128 cols + pad)
#define VLD 72      // bf16 ld for V2 (64 cols + pad)
#define PLD 392     // bf16 ld for P2 (384 cols + pad)

#define OFF_S   0
#define OFF_V   (OFF_S + 64 * SLD * 4)              // 33792
#define OFF_QK  (OFF_V + 384 * VLD * 2)             // 89088
#define OFF_Q   OFF_QK
#define OFF_K   (OFF_Q + 64 * QLD * 2)              // 114688
#define OFF_P   OFF_QK                               // aliases dead Q2/K2
#define SMEM_ATTN (OFF_K + 128 * QLD * 2)           // 165888

__global__ __launch_bounds__(256) void attn_wmma_kernel(
    const float* __restrict__ Q, const float* __restrict__ Kp,
    const float* __restrict__ Vp, const unsigned char* __restrict__ mask,
    float* __restrict__ Out)
{
    extern __shared__ __align__(256) char sm[];
    float*         sS  = (float*)(sm + OFF_S);
    __nv_bfloat16* sV2 = (__nv_bfloat16*)(sm + OFF_V);
    __nv_bfloat16* sQ2 = (__nv_bfloat16*)(sm + OFF_Q);
    __nv_bfloat16* sK2 = (__nv_bfloat16*)(sm + OFF_K);
    __nv_bfloat16* sP2 = (__nv_bfloat16*)(sm + OFF_P);

    const int l0 = blockIdx.x * 64;
    const int h  = blockIdx.y;
    const int b  = blockIdx.z;
    const int t  = threadIdx.x;
    const int w  = t >> 5;

    const size_t headoff = (size_t)h * EK_;
    const float* Qbase = Q  + (size_t)b * L_ * D_ + headoff;
    const float* Kbase = Kp + (size_t)b * L_ * D_ + headoff;
    const float* Vbase = Vp + (size_t)b * L_ * D_ + headoff;

    // ---- load + split Q (64 rows) ----
    for (int i = t; i < 64 * 64; i += 256) {
        int row = i >> 6, c = i & 63;
        float x = Qbase[(size_t)(l0 + row) * D_ + c];
        __nv_bfloat16 hi, lo;
        split2(x, hi, lo);
        __nv_bfloat16* r = sQ2 + row * QLD;
        r[c] = hi; r[64 + c] = hi; r[128 + c] = lo;
    }
    // ---- load + split K & V windows (128 rows, gl = l0-32+row) ----
    for (int i = t; i < 128 * 64; i += 256) {
        int row = i >> 6, c = i & 63;
        int gl = l0 - PADF + row;
        bool in = (gl >= 0) && (gl < L_);
        float xk = in ? Kbase[(size_t)gl * D_ + c] : 0.f;
        float xv = in ? Vbase[(size_t)gl * D_ + c] : 0.f;
        __nv_bfloat16 khi, klo, vhi, vlo;
        split2(xk, khi, klo);
        split2(xv, vhi, vlo);
        __nv_bfloat16* r = sK2 + row * QLD;
        r[c] = khi; r[64 + c] = klo; r[128 + c] = khi;
        sV2[row * VLD + c]         = vhi;
        sV2[(128 + row) * VLD + c] = vlo;
        sV2[(256 + row) * VLD + c] = vhi;
    }
    __syncthreads();

    // ---- S = Q2 @ K2^T : warp w -> row-tile (w>>1), col-tiles (w&1)*4+0..3 ----
    {
        const int rt = (w >> 1) * 16;
        const int c0 = (w & 1) * 4;
        wmma::fragment<wmma::accumulator, 16, 16, 16, float> sf[4];
        #pragma unroll
        for (int j = 0; j < 4; j++) wmma::fill_fragment(sf[j], 0.f);
        #pragma unroll
        for (int kk = 0; kk < 192; kk += 16) {
            wmma::fragment<wmma::matrix_a, 16, 16, 16, __nv_bfloat16,
                           wmma::row_major> qa;
            wmma::load_matrix_sync(qa, sQ2 + rt * QLD + kk, QLD);
            #pragma unroll
            for (int j = 0; j < 4; j++) {
                wmma::fragment<wmma::matrix_b, 16, 16, 16, __nv_bfloat16,
                               wmma::col_major> kb;
                wmma::load_matrix_sync(kb, sK2 + (c0 + j) * 16 * QLD + kk, QLD);
                wmma::mma_sync(sf[j], qa, kb, sf[j]);
            }
        }
        #pragma unroll
        for (int j = 0; j < 4; j++)
            wmma::store_matrix_sync(sS + rt * SLD + (c0 + j) * 16, sf[j],
                                    SLD, wmma::mem_row_major);
    }
    __syncthreads();

    // ---- softmax per query row over the 64-wide band; write split P2 ----
    {
        const int g     = t >> 2;      // query row 0..63
        const int lane4 = t & 3;       // owns cols [lane4*32, lane4*32+32)
        const int c0    = lane4 * 32;
        const unsigned char* mrow = mask + (size_t)b * L_;

        float sv[32];
        #pragma unroll
        for (int i = 0; i < 32; i++) {
            int j  = c0 + i;
            int k  = j - g;
            int gl = l0 + j - PADF;
            bool valid = (k >= 0) && (k < 64) && (gl >= 0) && (gl < L_)
                         && (mrow[gl] == 0);
            sv[i] = valid ? sS[g * SLD + j] : -1e30f;
        }
        float m = sv[0];
        #pragma unroll
        for (int i = 1; i < 32; i++) m = fmaxf(m, sv[i]);
        m = fmaxf(m, __shfl_xor_sync(0xffffffffu, m, 1));
        m = fmaxf(m, __shfl_xor_sync(0xffffffffu, m, 2));
        float sum = 0.f;
        #pragma unroll
        for (int i = 0; i < 32; i++) { sv[i] = __expf(sv[i] - m); sum += sv[i]; }
        sum += __shfl_xor_sync(0xffffffffu, sum, 1);
        sum += __shfl_xor_sync(0xffffffffu, sum, 2);
        float inv = 1.f / sum;
        __nv_bfloat16* pr = sP2 + g * PLD;
        #pragma unroll
        for (int i = 0; i < 32; i++) {
            int j = c0 + i;
            __nv_bfloat16 hi, lo;
            split2(sv[i] * inv, hi, lo);
            pr[j] = hi; pr[128 + j] = hi; pr[256 + j] = lo;
        }
    }
    __syncthreads();

    // ---- O = P2 @ V2 : warp w -> row-tile (w>>1), col-tiles (w&1)*2+0..1 ----
    {
        const int rt = (w >> 1) * 16;
        const int c0 = (w & 1) * 2;
        wmma::fragment<wmma::accumulator, 16, 16, 16, float> of[2];
        #pragma unroll
        for (int j = 0; j < 2; j++) wmma::fill_fragment(of[j], 0.f);
        #pragma unroll
        for (int kk = 0; kk < 384; kk += 16) {
            wmma::fragment<wmma::matrix_a, 16, 16, 16, __nv_bfloat16,
                           wmma::row_major> pa;
            wmma::load_matrix_sync(pa, sP2 + rt * PLD + kk, PLD);
            #pragma unroll
            for (int j = 0; j < 2; j++) {
                wmma::fragment<wmma::matrix_b, 16, 16, 16, __nv_bfloat16,
                               wmma::row_major> vb;
                wmma::load_matrix_sync(vb, sV2 + kk * VLD + (c0 + j) * 16, VLD);
                wmma::mma_sync(of[j], pa, vb, of[j]);
            }
        }
        float* obase = Out + ((size_t)b * L_ + l0 + rt) * D_ + headoff;
        #pragma unroll
        for (int j = 0; j < 2; j++)
            wmma::store_matrix_sync(obase + (c0 + j) * 16, of[j],
                                    D_, wmma::mem_row_major);
    }
}

// ---------------------------------------------------------------------------
// Launch
// ---------------------------------------------------------------------------
extern "C" void kernel_launch(void* const* d_in, const int* in_sizes, int n_in,
                              void* d_out, int out_size)
{
    const float* query = (const float*)d_in[0];
    const float* key   = (const float*)d_in[1];
    const float* value = (const float*)d_in[2];
    const unsigned char* mask = (const unsigned char*)d_in[3];
    const float* Wq = (const float*)d_in[5];
    const float* Wk = (const float*)d_in[6];
    const float* Wv = (const float*)d_in[7];
    const float* Wo = (const float*)d_in[8];
    float* out = (float*)d_out;

    float *dq, *dk, *dv, *da;
    __nv_bfloat16 *din2, *dat2, *dw2;
    cudaGetSymbolAddress((void**)&dq, g_q);
    cudaGetSymbolAddress((void**)&dk, g_k);
    cudaGetSymbolAddress((void**)&dv, g_v);
    cudaGetSymbolAddress((void**)&da, g_attn);
    cudaGetSymbolAddress((void**)&din2, g_in2);
    cudaGetSymbolAddress((void**)&dat2, g_attn2);
    cudaGetSymbolAddress((void**)&dw2, g_w2);

    cudaFuncSetAttribute(attn_wmma_kernel,
                         cudaFuncAttributeMaxDynamicSharedMemorySize, SMEM_ATTN);

    // 1) split inputs + weights into compensated bf16 layouts
    split_in_kernel<<<dim3(M_ * D_ / 256, 3), 256>>>(query, key, value);
    split_w_kernel<<<dim3(8, 8, 4), 256>>>(Wq, Wk, Wv, Wo);

    // 2) QKV projections: 3 GEMMs in one tensor-core launch
    const __nv_bfloat16* Aq = din2;
    const __nv_bfloat16* Ak = din2 + (size_t)1 * M_ * K2_;
    const __nv_bfloat16* Av = din2 + (size_t)2 * M_ * K2_;
    const __nv_bfloat16* Bq = dw2;
    const __nv_bfloat16* Bk = dw2 + (size_t)1 * D_ * K2_;
    const __nv_bfloat16* Bv = dw2 + (size_t)2 * D_ * K2_;
    const __nv_bfloat16* Bo = dw2 + (size_t)3 * D_ * K2_;
    gemm3_kernel<<<dim3(D_ / BN, M_ / BM, 3), 256>>>(Aq, Ak, Av, Bq, Bk, Bv,
                                                     dq, dk, dv);

    // 3) local attention (wmma, compensated bf16)
    attn_wmma_kernel<<<dim3(16, 8, 4), 256, SMEM_ATTN>>>(dq, dk, dv, mask, da);

    // 4) split attention output, then output projection
    split_attn_kernel<<<M_ * D_ / 256, 256>>>();
    gemm3_kernel<<<dim3(D_ / BN, M_ / BM, 1), 256>>>(dat2, dat2, dat2,
                                                     Bo, Bo, Bo, out, out, out);
}

// round 7
// speedup vs baseline: 1.8928x; 1.1783x over previous
#include <cuda_runtime.h>
#include <cuda_bf16.h>
#include <mma.h>
#include <cstdint>
#include <cstddef>

using namespace nvcuda;

// Problem constants
#define B_   4
#define L_   1024
#define D_   512
#define H_   8
#define EK_  64
#define PADF 32
#define M_   (B_ * L_)    // 4096
#define K2_  1536         // K tripled: [hi|hi|lo] x [hi|lo|hi] compensated layout

// ---------------------------------------------------------------------------
// Scratch (device globals -- no runtime allocation allowed)
// ---------------------------------------------------------------------------
__device__ float g_q[M_ * D_];
__device__ float g_k[M_ * D_];
__device__ float g_v[M_ * D_];
__device__ __align__(256) __nv_bfloat16 g_in2[3ull * M_ * K2_];  // split q,k,v
__device__ __align__(256) __nv_bfloat16 g_attn2[(size_t)M_ * K2_];
__device__ __align__(256) __nv_bfloat16 g_w2[4ull * D_ * K2_];   // split+T weights

// ---------------------------------------------------------------------------
// 2-way split: x = hi + lo (bf16 each).
// ---------------------------------------------------------------------------
__device__ __forceinline__ void split2(float x, __nv_bfloat16& hi,
                                       __nv_bfloat16& lo)
{
    hi = __float2bfloat16(x);
    lo = __float2bfloat16(x - __bfloat162float(hi));
}

__global__ __launch_bounds__(256) void split_in_kernel(
    const float* __restrict__ q, const float* __restrict__ k,
    const float* __restrict__ v)
{
    int i = blockIdx.x * 256 + threadIdx.x;           // over M_*D_
    int s = blockIdx.y;
    const float* S = (s == 0) ? q : (s == 1) ? k : v;
    float x = S[i];
    __nv_bfloat16 hi, lo;
    split2(x, hi, lo);
    int r = i >> 9, c = i & 511;
    __nv_bfloat16* dst = g_in2 + (size_t)s * M_ * K2_ + (size_t)r * K2_;
    dst[c]        = hi;   // pairs with w_hi
    dst[512 + c]  = hi;   // pairs with w_lo
    dst[1024 + c] = lo;   // pairs with w_hi
}

// Weights: W[K=512][N=512] row-major -> Wt[n][j]=hi, Wt[n][512+j]=lo, [1024+j]=hi
__global__ __launch_bounds__(256) void split_w_kernel(
    const float* __restrict__ Wq, const float* __restrict__ Wk,
    const float* __restrict__ Wv, const float* __restrict__ Wo)
{
    __shared__ float tile[64][65];
    int z = blockIdx.z;
    const float* W = (z == 0) ? Wq : (z == 1) ? Wk : (z == 2) ? Wv : Wo;
    int j0 = blockIdx.x * 64, n0 = blockIdx.y * 64;
    for (int i = threadIdx.x; i < 4096; i += 256) {
        int r = i >> 6, c = i & 63;
        tile[r][c] = W[(size_t)(j0 + r) * D_ + n0 + c];
    }
    __syncthreads();
    __nv_bfloat16* dst = g_w2 + (size_t)z * D_ * K2_;
    for (int i = threadIdx.x; i < 4096; i += 256) {
        int r = i >> 6, c = i & 63;           // r: local n, c: local j
        float x = tile[c][r];
        __nv_bfloat16 hi, lo;
        split2(x, hi, lo);
        __nv_bfloat16* row = dst + (size_t)(n0 + r) * K2_;
        row[j0 + c]        = hi;
        row[512 + j0 + c]  = lo;
        row[1024 + j0 + c] = hi;
    }
}

// ---------------------------------------------------------------------------
// wmma bf16 GEMM: C[M_,512] = A2[M_,1536] @ Wt[512,1536]^T
// Block tile 128x128, 8 warps, K-chunk 64, 2-stage cp.async, dynamic smem.
// ---------------------------------------------------------------------------
#define BM 128
#define BN 128
#define BK 64
#define STR 72                       // smem row stride (bf16), 144B
#define NKT (K2_ / BK)               // 24
#define TILE_ELEMS (128 * STR)       // 9216
#define GEMM_SMEM (4 * TILE_ELEMS * 2)   // 73728 B

__device__ __forceinline__ void cp16(uint32_t dst, const void* src) {
    asm volatile("cp.async.cg.shared.global [%0], [%1], 16;"
                 :: "r"(dst), "l"(src));
}

__device__ __forceinline__ uint32_t smem_u32(const void* p) {
    uint32_t a;
    asm("{ .reg .u64 t; cvta.to.shared.u64 t, %1; cvt.u32.u64 %0, t; }"
        : "=r"(a) : "l"(p));
    return a;
}

// Load one 128x64 bf16 tile (rows K2_-strided) into smem stage.
__device__ __forceinline__ void tile_loads(const __nv_bfloat16* __restrict__ G,
                                           uint32_t sbase, int t)
{
    #pragma unroll
    for (int i = 0; i < 4; i++) {
        int idx = t + i * 256;              // 0..1023 chunks of 16B
        int row = idx >> 3, c = idx & 7;
        cp16(sbase + (uint32_t)(row * (STR * 2) + c * 16),
             G + (size_t)row * K2_ + c * 8);
    }
}

__global__ __launch_bounds__(256) void gemm3_kernel(
    const __nv_bfloat16* __restrict__ A0, const __nv_bfloat16* __restrict__ A1,
    const __nv_bfloat16* __restrict__ A2,
    const __nv_bfloat16* __restrict__ Bw0, const __nv_bfloat16* __restrict__ Bw1,
    const __nv_bfloat16* __restrict__ Bw2,
    float* __restrict__ C0, float* __restrict__ C1, float* __restrict__ C2)
{
    extern __shared__ __align__(256) __nv_bfloat16 gsm[];
    __nv_bfloat16* sA = gsm;                     // [2][TILE_ELEMS]
    __nv_bfloat16* sB = gsm + 2 * TILE_ELEMS;    // [2][TILE_ELEMS]

    const int z = blockIdx.z;
    const __nv_bfloat16* A  = (z == 0) ? A0  : (z == 1) ? A1  : A2;
    const __nv_bfloat16* Bw = (z == 0) ? Bw0 : (z == 1) ? Bw1 : Bw2;
    float* C                = (z == 0) ? C0  : (z == 1) ? C1  : C2;

    const int t   = threadIdx.x;
    const int wid = t >> 5;
    const int wm  = wid & 1;
    const int wn  = wid >> 1;
    const int m0  = blockIdx.y * BM, n0 = blockIdx.x * BN;

    const __nv_bfloat16* Abase = A  + (size_t)m0 * K2_;
    const __nv_bfloat16* Bbase = Bw + (size_t)n0 * K2_;
    const uint32_t sAb = smem_u32(sA), sBb = smem_u32(sB);
    const uint32_t stage_bytes = TILE_ELEMS * 2;

    wmma::fragment<wmma::accumulator, 16, 16, 16, float> cf[4][2];
    #pragma unroll
    for (int i = 0; i < 4; i++)
        #pragma unroll
        for (int j = 0; j < 2; j++) wmma::fill_fragment(cf[i][j], 0.f);

    tile_loads(Abase, sAb, t);
    tile_loads(Bbase, sBb, t);
    asm volatile("cp.async.commit_group;");

    #pragma unroll 1
    for (int kt = 0; kt < NKT; kt++) {
        const int s = kt & 1;
        if (kt + 1 < NKT) {
            const int so = s ^ 1;
            tile_loads(Abase + (kt + 1) * BK, sAb + so * stage_bytes, t);
            tile_loads(Bbase + (kt + 1) * BK, sBb + so * stage_bytes, t);
            asm volatile("cp.async.commit_group;");
            asm volatile("cp.async.wait_group 1;");
        } else {
            asm volatile("cp.async.wait_group 0;");
        }
        __syncthreads();

        const __nv_bfloat16* sa = sA + s * TILE_ELEMS;
        const __nv_bfloat16* sb = sB + s * TILE_ELEMS;
        #pragma unroll
        for (int kk = 0; kk < BK; kk += 16) {
            wmma::fragment<wmma::matrix_a, 16, 16, 16, __nv_bfloat16,
                           wmma::row_major> af[4];
            wmma::fragment<wmma::matrix_b, 16, 16, 16, __nv_bfloat16,
                           wmma::col_major> bf[2];
            #pragma unroll
            for (int i = 0; i < 4; i++)
                wmma::load_matrix_sync(af[i],
                    sa + (wm * 64 + i * 16) * STR + kk, STR);
            #pragma unroll
            for (int j = 0; j < 2; j++)
                wmma::load_matrix_sync(bf[j],
                    sb + (wn * 32 + j * 16) * STR + kk, STR);
            #pragma unroll
            for (int i = 0; i < 4; i++)
                #pragma unroll
                for (int j = 0; j < 2; j++)
                    wmma::mma_sync(cf[i][j], af[i], bf[j], cf[i][j]);
        }
        __syncthreads();
    }

    #pragma unroll
    for (int i = 0; i < 4; i++)
        #pragma unroll
        for (int j = 0; j < 2; j++)
            wmma::store_matrix_sync(
                C + (size_t)(m0 + wm * 64 + i * 16) * D_ + n0 + wn * 32 + j * 16,
                cf[i][j], D_, wmma::mem_row_major);
}

// ---------------------------------------------------------------------------
// wmma banded local attention. Grid (16, 8, 4), 256 threads, 113.7KB smem
// -> 2 CTAs/SM. For 16-row group G the valid window is cols [16G, 16G+80):
// S and P are stored banded (80 cols). Compensated bf16 via 3 MMA passes.
// Epilogue writes split O directly to g_attn2 (no separate split kernel).
// ---------------------------------------------------------------------------
#define AQLD 72
#define ASLD 84      // fp32 banded S: 80 + 4
#define APLD 88      // bf16 banded P: 80 + 8
#define AOLD 68      // fp32 staged O: 64 + 4

#define AOFF_Q 0                                   // Qhi,Qlo [64][72]
#define AOFF_K (AOFF_Q + 2 * 64 * AQLD * 2)        // 18432: Khi,Klo [128][72]
#define AOFF_V (AOFF_K + 2 * 128 * AQLD * 2)       // 55296: Vhi,Vlo [128][72]
#define AOFF_S (AOFF_V + 2 * 128 * AQLD * 2)       // 92160: S [64][84] fp32
#define SMEM_ATTN (AOFF_S + 64 * ASLD * 4)         // 113664

__global__ __launch_bounds__(256) void attn_wmma_kernel(
    const float* __restrict__ Q, const float* __restrict__ Kp,
    const float* __restrict__ Vp, const unsigned char* __restrict__ mask,
    __nv_bfloat16* __restrict__ Out2)
{
    extern __shared__ __align__(256) char sm[];
    __nv_bfloat16* sQhi = (__nv_bfloat16*)(sm + AOFF_Q);
    __nv_bfloat16* sQlo = sQhi + 64 * AQLD;
    __nv_bfloat16* sKhi = (__nv_bfloat16*)(sm + AOFF_K);
    __nv_bfloat16* sKlo = sKhi + 128 * AQLD;
    __nv_bfloat16* sVhi = (__nv_bfloat16*)(sm + AOFF_V);
    __nv_bfloat16* sVlo = sVhi + 128 * AQLD;
    float*         sS   = (float*)(sm + AOFF_S);
    // P aliases dead Q+K region (needs 22528 B <= 55296 B)
    __nv_bfloat16* sPhi = (__nv_bfloat16*)(sm + AOFF_Q);
    __nv_bfloat16* sPlo = sPhi + 64 * APLD;
    float*         sO   = sS;                      // [64][68], aliases dead S

    const int l0 = blockIdx.x * 64;
    const int h  = blockIdx.y;
    const int b  = blockIdx.z;
    const int t  = threadIdx.x;
    const int w  = t >> 5;

    const size_t headoff = (size_t)h * EK_;
    const float* Qbase = Q  + (size_t)b * L_ * D_ + headoff;
    const float* Kbase = Kp + (size_t)b * L_ * D_ + headoff;
    const float* Vbase = Vp + (size_t)b * L_ * D_ + headoff;

    // ---- load + split Q (64 rows) ----
    for (int i = t; i < 64 * 64; i += 256) {
        int row = i >> 6, c = i & 63;
        float x = Qbase[(size_t)(l0 + row) * D_ + c];
        __nv_bfloat16 hi, lo;
        split2(x, hi, lo);
        sQhi[row * AQLD + c] = hi;
        sQlo[row * AQLD + c] = lo;
    }
    // ---- load + split K & V windows (128 rows, gl = l0-32+row) ----
    for (int i = t; i < 128 * 64; i += 256) {
        int row = i >> 6, c = i & 63;
        int gl = l0 - PADF + row;
        bool in = (gl >= 0) && (gl < L_);
        float xk = in ? Kbase[(size_t)gl * D_ + c] : 0.f;
        float xv = in ? Vbase[(size_t)gl * D_ + c] : 0.f;
        __nv_bfloat16 khi, klo, vhi, vlo;
        split2(xk, khi, klo);
        split2(xv, vhi, vlo);
        sKhi[row * AQLD + c] = khi;
        sKlo[row * AQLD + c] = klo;
        sVhi[row * AQLD + c] = vhi;
        sVlo[row * AQLD + c] = vlo;
    }
    __syncthreads();

    // ---- S (banded): row group rg = w>>1, col tiles split 3/2 across halves.
    // S_rel[g][r] = Q[g] . K[16*rg + r], r in [0,80)
    {
        const int rg   = w >> 1;
        const int half = w & 1;
        const int j0   = half ? 3 : 0;
        const int nj   = half ? 2 : 3;

        wmma::fragment<wmma::accumulator, 16, 16, 16, float> sf[3];
        #pragma unroll
        for (int j = 0; j < 3; j++) wmma::fill_fragment(sf[j], 0.f);

        #pragma unroll
        for (int tm = 0; tm < 3; tm++) {
            const __nv_bfloat16* Qsrc = (tm == 2) ? sQlo : sQhi;
            const __nv_bfloat16* Ksrc = (tm == 1) ? sKlo : sKhi;
            #pragma unroll
            for (int kk = 0; kk < 64; kk += 16) {
                wmma::fragment<wmma::matrix_a, 16, 16, 16, __nv_bfloat16,
                               wmma::row_major> qa;
                wmma::load_matrix_sync(qa, Qsrc + rg * 16 * AQLD + kk, AQLD);
                #pragma unroll
                for (int j = 0; j < 3; j++) {
                    if (j < nj) {
                        wmma::fragment<wmma::matrix_b, 16, 16, 16, __nv_bfloat16,
                                       wmma::col_major> kb;
                        wmma::load_matrix_sync(kb,
                            Ksrc + (rg * 16 + (j0 + j) * 16) * AQLD + kk, AQLD);
                        wmma::mma_sync(sf[j], qa, kb, sf[j]);
                    }
                }
            }
        }
        #pragma unroll
        for (int j = 0; j < 3; j++)
            if (j < nj)
                wmma::store_matrix_sync(sS + rg * 16 * ASLD + (j0 + j) * 16,
                                        sf[j], ASLD, wmma::mem_row_major);
    }
    __syncthreads();

    // ---- softmax per query row; write banded split P ----
    {
        const int g     = t >> 2;      // query row 0..63
        const int lane4 = t & 3;
        const int G     = g >> 4;
        const int off   = g & 15;      // valid rel start; valid r in [off, off+64)
        const int gl0   = l0 - PADF + 16 * G;
        const unsigned char* mrow = mask + (size_t)b * L_;

        float sv[16];
        #pragma unroll
        for (int i = 0; i < 16; i++) {
            int r  = off + lane4 * 16 + i;
            int gl = gl0 + r;
            bool valid = (gl >= 0) && (gl < L_) && (mrow[gl] == 0);
            sv[i] = valid ? sS[g * ASLD + r] : -1e30f;
        }
        float m = sv[0];
        #pragma unroll
        for (int i = 1; i < 16; i++) m = fmaxf(m, sv[i]);
        m = fmaxf(m, __shfl_xor_sync(0xffffffffu, m, 1));
        m = fmaxf(m, __shfl_xor_sync(0xffffffffu, m, 2));
        float sum = 0.f;
        #pragma unroll
        for (int i = 0; i < 16; i++) { sv[i] = __expf(sv[i] - m); sum += sv[i]; }
        sum += __shfl_xor_sync(0xffffffffu, sum, 1);
        sum += __shfl_xor_sync(0xffffffffu, sum, 2);
        float inv = 1.f / sum;

        // zero full 80-wide band first (warp-synchronous, same-warp rows)
        __nv_bfloat16 z0 = __float2bfloat16(0.f);
        #pragma unroll
        for (int i = 0; i < 20; i++) {
            int r = lane4 * 20 + i;
            sPhi[g * APLD + r] = z0;
            sPlo[g * APLD + r] = z0;
        }
        #pragma unroll
        for (int i = 0; i < 16; i++) {
            int r = off + lane4 * 16 + i;
            __nv_bfloat16 hi, lo;
            split2(sv[i] * inv, hi, lo);
            sPhi[g * APLD + r] = hi;
            sPlo[g * APLD + r] = lo;
        }
    }
    __syncthreads();

    // ---- O = P @ V (banded, compensated): rg = w>>1, col tiles (w&1)*2+j ----
    {
        const int rg   = w >> 1;
        const int half = w & 1;

        wmma::fragment<wmma::accumulator, 16, 16, 16, float> of[2];
        #pragma unroll
        for (int j = 0; j < 2; j++) wmma::fill_fragment(of[j], 0.f);

        #pragma unroll
        for (int tm = 0; tm < 3; tm++) {
            const __nv_bfloat16* Psrc = (tm == 2) ? sPlo : sPhi;
            const __nv_bfloat16* Vsrc = (tm == 1) ? sVlo : sVhi;
            #pragma unroll
            for (int kk = 0; kk < 80; kk += 16) {
                wmma::fragment<wmma::matrix_a, 16, 16, 16, __nv_bfloat16,
                               wmma::row_major> pa;
                wmma::load_matrix_sync(pa, Psrc + rg * 16 * APLD + kk, APLD);
                #pragma unroll
                for (int j = 0; j < 2; j++) {
                    wmma::fragment<wmma::matrix_b, 16, 16, 16, __nv_bfloat16,
                                   wmma::row_major> vb;
                    wmma::load_matrix_sync(vb,
                        Vsrc + (rg * 16 + kk) * AQLD + (half * 2 + j) * 16, AQLD);
                    wmma::mma_sync(of[j], pa, vb, of[j]);
                }
            }
        }
        #pragma unroll
        for (int j = 0; j < 2; j++)
            wmma::store_matrix_sync(sO + rg * 16 * AOLD + (half * 2 + j) * 16,
                                    of[j], AOLD, wmma::mem_row_major);
    }
    __syncthreads();

    // ---- epilogue: split O straight into g_attn2 [hi|hi|lo] layout ----
    for (int i = t; i < 64 * 64; i += 256) {
        int row = i >> 6, c = i & 63;
        float x = sO[row * AOLD + c];
        __nv_bfloat16 hi, lo;
        split2(x, hi, lo);
        __nv_bfloat16* dst = Out2 + (size_t)(b * L_ + l0 + row) * K2_;
        int c2 = (int)headoff + c;
        dst[c2]        = hi;
        dst[512 + c2]  = hi;
        dst[1024 + c2] = lo;
    }
}

// ---------------------------------------------------------------------------
// Launch
// ---------------------------------------------------------------------------
extern "C" void kernel_launch(void* const* d_in, const int* in_sizes, int n_in,
                              void* d_out, int out_size)
{
    const float* query = (const float*)d_in[0];
    const float* key   = (const float*)d_in[1];
    const float* value = (const float*)d_in[2];
    const unsigned char* mask = (const unsigned char*)d_in[3];
    const float* Wq = (const float*)d_in[5];
    const float* Wk = (const float*)d_in[6];
    const float* Wv = (const float*)d_in[7];
    const float* Wo = (const float*)d_in[8];
    float* out = (float*)d_out;

    float *dq, *dk, *dv;
    __nv_bfloat16 *din2, *dat2, *dw2;
    cudaGetSymbolAddress((void**)&dq, g_q);
    cudaGetSymbolAddress((void**)&dk, g_k);
    cudaGetSymbolAddress((void**)&dv, g_v);
    cudaGetSymbolAddress((void**)&din2, g_in2);
    cudaGetSymbolAddress((void**)&dat2, g_attn2);
    cudaGetSymbolAddress((void**)&dw2, g_w2);

    cudaFuncSetAttribute(attn_wmma_kernel,
                         cudaFuncAttributeMaxDynamicSharedMemorySize, SMEM_ATTN);
    cudaFuncSetAttribute(gemm3_kernel,
                         cudaFuncAttributeMaxDynamicSharedMemorySize, GEMM_SMEM);

    // 1) split inputs + weights into compensated bf16 layouts
    split_in_kernel<<<dim3(M_ * D_ / 256, 3), 256>>>(query, key, value);
    split_w_kernel<<<dim3(8, 8, 4), 256>>>(Wq, Wk, Wv, Wo);

    // 2) QKV projections: 3 GEMMs in one tensor-core launch
    const __nv_bfloat16* Aq = din2;
    const __nv_bfloat16* Ak = din2 + (size_t)1 * M_ * K2_;
    const __nv_bfloat16* Av = din2 + (size_t)2 * M_ * K2_;
    const __nv_bfloat16* Bq = dw2;
    const __nv_bfloat16* Bk = dw2 + (size_t)1 * D_ * K2_;
    const __nv_bfloat16* Bv = dw2 + (size_t)2 * D_ * K2_;
    const __nv_bfloat16* Bo = dw2 + (size_t)3 * D_ * K2_;
    gemm3_kernel<<<dim3(D_ / BN, M_ / BM, 3), 256, GEMM_SMEM>>>(
        Aq, Ak, Av, Bq, Bk, Bv, dq, dk, dv);

    // 3) banded local attention (wmma); writes split O directly
    attn_wmma_kernel<<<dim3(16, 8, 4), 256, SMEM_ATTN>>>(dq, dk, dv, mask, dat2);

    // 4) output projection
    gemm3_kernel<<<dim3(D_ / BN, M_ / BM, 1), 256, GEMM_SMEM>>>(
        dat2, dat2, dat2, Bo, Bo, Bo, out, out, out);
}

// round 8
// speedup vs baseline: 2.1364x; 1.1287x over previous
#include <cuda_runtime.h>
#include <cuda_bf16.h>
#include <mma.h>
#include <cstdint>
#include <cstddef>

using namespace nvcuda;

// Problem constants
#define B_   4
#define L_   1024
#define D_   512
#define H_   8
#define EK_  64
#define PADF 32
#define M_   (B_ * L_)    // 4096
#define K2_  1536         // K tripled: [hi|hi|lo] x [hi|lo|hi] compensated layout

// ---------------------------------------------------------------------------
// Scratch (device globals -- no runtime allocation allowed)
// ---------------------------------------------------------------------------
__device__ float g_q[M_ * D_];
__device__ float g_k[M_ * D_];
__device__ float g_v[M_ * D_];
__device__ __align__(256) __nv_bfloat16 g_in2[3ull * M_ * K2_];  // split q,k,v
__device__ __align__(256) __nv_bfloat16 g_attn2[(size_t)M_ * K2_];
__device__ __align__(256) __nv_bfloat16 g_w2[4ull * D_ * K2_];   // split+T weights

// ---------------------------------------------------------------------------
// 2-way split: x = hi + lo (bf16 each).
// ---------------------------------------------------------------------------
__device__ __forceinline__ void split2(float x, __nv_bfloat16& hi,
                                       __nv_bfloat16& lo)
{
    hi = __float2bfloat16(x);
    lo = __float2bfloat16(x - __bfloat162float(hi));
}

__global__ __launch_bounds__(256) void split_in_kernel(
    const float* __restrict__ q, const float* __restrict__ k,
    const float* __restrict__ v)
{
    int i = blockIdx.x * 256 + threadIdx.x;           // over M_*D_
    int s = blockIdx.y;
    const float* S = (s == 0) ? q : (s == 1) ? k : v;
    float x = S[i];
    __nv_bfloat16 hi, lo;
    split2(x, hi, lo);
    int r = i >> 9, c = i & 511;
    __nv_bfloat16* dst = g_in2 + (size_t)s * M_ * K2_ + (size_t)r * K2_;
    dst[c]        = hi;   // pairs with w_hi
    dst[512 + c]  = hi;   // pairs with w_lo
    dst[1024 + c] = lo;   // pairs with w_hi
}

// Weights: W[K=512][N=512] row-major -> Wt[n][j]=hi, Wt[n][512+j]=lo, [1024+j]=hi
__global__ __launch_bounds__(256) void split_w_kernel(
    const float* __restrict__ Wq, const float* __restrict__ Wk,
    const float* __restrict__ Wv, const float* __restrict__ Wo)
{
    __shared__ float tile[64][65];
    int z = blockIdx.z;
    const float* W = (z == 0) ? Wq : (z == 1) ? Wk : (z == 2) ? Wv : Wo;
    int j0 = blockIdx.x * 64, n0 = blockIdx.y * 64;
    for (int i = threadIdx.x; i < 4096; i += 256) {
        int r = i >> 6, c = i & 63;
        tile[r][c] = W[(size_t)(j0 + r) * D_ + n0 + c];
    }
    __syncthreads();
    __nv_bfloat16* dst = g_w2 + (size_t)z * D_ * K2_;
    for (int i = threadIdx.x; i < 4096; i += 256) {
        int r = i >> 6, c = i & 63;           // r: local n, c: local j
        float x = tile[c][r];
        __nv_bfloat16 hi, lo;
        split2(x, hi, lo);
        __nv_bfloat16* row = dst + (size_t)(n0 + r) * K2_;
        row[j0 + c]        = hi;
        row[512 + j0 + c]  = lo;
        row[1024 + j0 + c] = hi;
    }
}

// ---------------------------------------------------------------------------
// wmma bf16 GEMM: C[M_,512] = A2[M_,1536] @ Wt[512,1536]^T
// Block tile 128x128, 8 warps, K-chunk 64, 2-stage cp.async, dynamic smem.
// ---------------------------------------------------------------------------
#define BM 128
#define BN 128
#define BK 64
#define STR 72                       // smem row stride (bf16), 144B
#define NKT (K2_ / BK)               // 24
#define TILE_ELEMS (128 * STR)       // 9216
#define GEMM_SMEM (4 * TILE_ELEMS * 2)   // 73728 B

__device__ __forceinline__ void cp16(uint32_t dst, const void* src) {
    asm volatile("cp.async.cg.shared.global [%0], [%1], 16;"
                 :: "r"(dst), "l"(src));
}

__device__ __forceinline__ uint32_t smem_u32(const void* p) {
    uint32_t a;
    asm("{ .reg .u64 t; cvta.to.shared.u64 t, %1; cvt.u32.u64 %0, t; }"
        : "=r"(a) : "l"(p));
    return a;
}

// Load one 128x64 bf16 tile (rows K2_-strided) into smem stage.
__device__ __forceinline__ void tile_loads(const __nv_bfloat16* __restrict__ G,
                                           uint32_t sbase, int t)
{
    #pragma unroll
    for (int i = 0; i < 4; i++) {
        int idx = t + i * 256;              // 0..1023 chunks of 16B
        int row = idx >> 3, c = idx & 7;
        cp16(sbase + (uint32_t)(row * (STR * 2) + c * 16),
             G + (size_t)row * K2_ + c * 8);
    }
}

__global__ __launch_bounds__(256, 2) void gemm3_kernel(
    const __nv_bfloat16* __restrict__ A0, const __nv_bfloat16* __restrict__ A1,
    const __nv_bfloat16* __restrict__ A2,
    const __nv_bfloat16* __restrict__ Bw0, const __nv_bfloat16* __restrict__ Bw1,
    const __nv_bfloat16* __restrict__ Bw2,
    float* __restrict__ C0, float* __restrict__ C1, float* __restrict__ C2)
{
    extern __shared__ __align__(256) __nv_bfloat16 gsm[];
    __nv_bfloat16* sA = gsm;                     // [2][TILE_ELEMS]
    __nv_bfloat16* sB = gsm + 2 * TILE_ELEMS;    // [2][TILE_ELEMS]

    const int z = blockIdx.z;
    const __nv_bfloat16* A  = (z == 0) ? A0  : (z == 1) ? A1  : A2;
    const __nv_bfloat16* Bw = (z == 0) ? Bw0 : (z == 1) ? Bw1 : Bw2;
    float* C                = (z == 0) ? C0  : (z == 1) ? C1  : C2;

    const int t   = threadIdx.x;
    const int wid = t >> 5;
    const int wm  = wid & 1;
    const int wn  = wid >> 1;
    const int m0  = blockIdx.y * BM, n0 = blockIdx.x * BN;

    const __nv_bfloat16* Abase = A  + (size_t)m0 * K2_;
    const __nv_bfloat16* Bbase = Bw + (size_t)n0 * K2_;
    const uint32_t sAb = smem_u32(sA), sBb = smem_u32(sB);
    const uint32_t stage_bytes = TILE_ELEMS * 2;

    wmma::fragment<wmma::accumulator, 16, 16, 16, float> cf[4][2];
    #pragma unroll
    for (int i = 0; i < 4; i++)
        #pragma unroll
        for (int j = 0; j < 2; j++) wmma::fill_fragment(cf[i][j], 0.f);

    tile_loads(Abase, sAb, t);
    tile_loads(Bbase, sBb, t);
    asm volatile("cp.async.commit_group;");

    #pragma unroll 1
    for (int kt = 0; kt < NKT; kt++) {
        const int s = kt & 1;
        if (kt + 1 < NKT) {
            const int so = s ^ 1;
            tile_loads(Abase + (kt + 1) * BK, sAb + so * stage_bytes, t);
            tile_loads(Bbase + (kt + 1) * BK, sBb + so * stage_bytes, t);
            asm volatile("cp.async.commit_group;");
            asm volatile("cp.async.wait_group 1;");
        } else {
            asm volatile("cp.async.wait_group 0;");
        }
        __syncthreads();

        const __nv_bfloat16* sa = sA + s * TILE_ELEMS;
        const __nv_bfloat16* sb = sB + s * TILE_ELEMS;
        #pragma unroll
        for (int kk = 0; kk < BK; kk += 16) {
            wmma::fragment<wmma::matrix_a, 16, 16, 16, __nv_bfloat16,
                           wmma::row_major> af[4];
            wmma::fragment<wmma::matrix_b, 16, 16, 16, __nv_bfloat16,
                           wmma::col_major> bf[2];
            #pragma unroll
            for (int i = 0; i < 4; i++)
                wmma::load_matrix_sync(af[i],
                    sa + (wm * 64 + i * 16) * STR + kk, STR);
            #pragma unroll
            for (int j = 0; j < 2; j++)
                wmma::load_matrix_sync(bf[j],
                    sb + (wn * 32 + j * 16) * STR + kk, STR);
            #pragma unroll
            for (int i = 0; i < 4; i++)
                #pragma unroll
                for (int j = 0; j < 2; j++)
                    wmma::mma_sync(cf[i][j], af[i], bf[j], cf[i][j]);
        }
        __syncthreads();
    }

    #pragma unroll
    for (int i = 0; i < 4; i++)
        #pragma unroll
        for (int j = 0; j < 2; j++)
            wmma::store_matrix_sync(
                C + (size_t)(m0 + wm * 64 + i * 16) * D_ + n0 + wn * 32 + j * 16,
                cf[i][j], D_, wmma::mem_row_major);
}

// ---------------------------------------------------------------------------
// wmma banded local attention. Grid (16, 8, 4), 256 threads, 113.7KB smem.
// __launch_bounds__(256, 2) caps regs at 128 -> 2 CTAs/SM.
// ---------------------------------------------------------------------------
#define AQLD 72
#define ASLD 84      // fp32 banded S: 80 + 4
#define APLD 88      // bf16 banded P: 80 + 8
#define AOLD 68      // fp32 staged O: 64 + 4

#define AOFF_Q 0                                   // Qhi,Qlo [64][72]
#define AOFF_K (AOFF_Q + 2 * 64 * AQLD * 2)        // 18432: Khi,Klo [128][72]
#define AOFF_V (AOFF_K + 2 * 128 * AQLD * 2)       // 55296: Vhi,Vlo [128][72]
#define AOFF_S (AOFF_V + 2 * 128 * AQLD * 2)       // 92160: S [64][84] fp32
#define SMEM_ATTN (AOFF_S + 64 * ASLD * 4)         // 113664

__global__ __launch_bounds__(256, 2) void attn_wmma_kernel(
    const float* __restrict__ Q, const float* __restrict__ Kp,
    const float* __restrict__ Vp, const unsigned char* __restrict__ mask,
    __nv_bfloat16* __restrict__ Out2)
{
    extern __shared__ __align__(256) char sm[];
    __nv_bfloat16* sQhi = (__nv_bfloat16*)(sm + AOFF_Q);
    __nv_bfloat16* sQlo = sQhi + 64 * AQLD;
    __nv_bfloat16* sKhi = (__nv_bfloat16*)(sm + AOFF_K);
    __nv_bfloat16* sKlo = sKhi + 128 * AQLD;
    __nv_bfloat16* sVhi = (__nv_bfloat16*)(sm + AOFF_V);
    __nv_bfloat16* sVlo = sVhi + 128 * AQLD;
    float*         sS   = (float*)(sm + AOFF_S);
    // P aliases dead Q+K region (needs 22528 B <= 55296 B)
    __nv_bfloat16* sPhi = (__nv_bfloat16*)(sm + AOFF_Q);
    __nv_bfloat16* sPlo = sPhi + 64 * APLD;
    float*         sO   = sS;                      // [64][68], aliases dead S

    const int l0 = blockIdx.x * 64;
    const int h  = blockIdx.y;
    const int b  = blockIdx.z;
    const int t  = threadIdx.x;
    const int w  = t >> 5;

    const size_t headoff = (size_t)h * EK_;
    const float* Qbase = Q  + (size_t)b * L_ * D_ + headoff;
    const float* Kbase = Kp + (size_t)b * L_ * D_ + headoff;
    const float* Vbase = Vp + (size_t)b * L_ * D_ + headoff;

    // ---- load + split Q (64 rows) ----
    for (int i = t; i < 64 * 64; i += 256) {
        int row = i >> 6, c = i & 63;
        float x = Qbase[(size_t)(l0 + row) * D_ + c];
        __nv_bfloat16 hi, lo;
        split2(x, hi, lo);
        sQhi[row * AQLD + c] = hi;
        sQlo[row * AQLD + c] = lo;
    }
    // ---- load + split K & V windows (128 rows, gl = l0-32+row) ----
    for (int i = t; i < 128 * 64; i += 256) {
        int row = i >> 6, c = i & 63;
        int gl = l0 - PADF + row;
        bool in = (gl >= 0) && (gl < L_);
        float xk = in ? Kbase[(size_t)gl * D_ + c] : 0.f;
        float xv = in ? Vbase[(size_t)gl * D_ + c] : 0.f;
        __nv_bfloat16 khi, klo, vhi, vlo;
        split2(xk, khi, klo);
        split2(xv, vhi, vlo);
        sKhi[row * AQLD + c] = khi;
        sKlo[row * AQLD + c] = klo;
        sVhi[row * AQLD + c] = vhi;
        sVlo[row * AQLD + c] = vlo;
    }
    __syncthreads();

    // ---- S (banded): row group rg = w>>1, col tiles split 3/2 across halves.
    {
        const int rg   = w >> 1;
        const int half = w & 1;
        const int j0   = half ? 3 : 0;
        const int nj   = half ? 2 : 3;

        wmma::fragment<wmma::accumulator, 16, 16, 16, float> sf[3];
        #pragma unroll
        for (int j = 0; j < 3; j++) wmma::fill_fragment(sf[j], 0.f);

        #pragma unroll
        for (int tm = 0; tm < 3; tm++) {
            const __nv_bfloat16* Qsrc = (tm == 2) ? sQlo : sQhi;
            const __nv_bfloat16* Ksrc = (tm == 1) ? sKlo : sKhi;
            #pragma unroll
            for (int kk = 0; kk < 64; kk += 16) {
                wmma::fragment<wmma::matrix_a, 16, 16, 16, __nv_bfloat16,
                               wmma::row_major> qa;
                wmma::load_matrix_sync(qa, Qsrc + rg * 16 * AQLD + kk, AQLD);
                #pragma unroll
                for (int j = 0; j < 3; j++) {
                    if (j < nj) {
                        wmma::fragment<wmma::matrix_b, 16, 16, 16, __nv_bfloat16,
                                       wmma::col_major> kb;
                        wmma::load_matrix_sync(kb,
                            Ksrc + (rg * 16 + (j0 + j) * 16) * AQLD + kk, AQLD);
                        wmma::mma_sync(sf[j], qa, kb, sf[j]);
                    }
                }
            }
        }
        #pragma unroll
        for (int j = 0; j < 3; j++)
            if (j < nj)
                wmma::store_matrix_sync(sS + rg * 16 * ASLD + (j0 + j) * 16,
                                        sf[j], ASLD, wmma::mem_row_major);
    }
    __syncthreads();

    // ---- softmax per query row; write banded split P ----
    {
        const int g     = t >> 2;      // query row 0..63
        const int lane4 = t & 3;
        const int G     = g >> 4;
        const int off   = g & 15;      // valid rel start; valid r in [off, off+64)
        const int gl0   = l0 - PADF + 16 * G;
        const unsigned char* mrow = mask + (size_t)b * L_;

        float sv[16];
        #pragma unroll
        for (int i = 0; i < 16; i++) {
            int r  = off + lane4 * 16 + i;
            int gl = gl0 + r;
            bool valid = (gl >= 0) && (gl < L_) && (mrow[gl] == 0);
            sv[i] = valid ? sS[g * ASLD + r] : -1e30f;
        }
        float m = sv[0];
        #pragma unroll
        for (int i = 1; i < 16; i++) m = fmaxf(m, sv[i]);
        m = fmaxf(m, __shfl_xor_sync(0xffffffffu, m, 1));
        m = fmaxf(m, __shfl_xor_sync(0xffffffffu, m, 2));
        float sum = 0.f;
        #pragma unroll
        for (int i = 0; i < 16; i++) { sv[i] = __expf(sv[i] - m); sum += sv[i]; }
        sum += __shfl_xor_sync(0xffffffffu, sum, 1);
        sum += __shfl_xor_sync(0xffffffffu, sum, 2);
        float inv = 1.f / sum;

        // zero full 80-wide band first (warp-synchronous, same-warp rows)
        __nv_bfloat16 z0 = __float2bfloat16(0.f);
        #pragma unroll
        for (int i = 0; i < 20; i++) {
            int r = lane4 * 20 + i;
            sPhi[g * APLD + r] = z0;
            sPlo[g * APLD + r] = z0;
        }
        #pragma unroll
        for (int i = 0; i < 16; i++) {
            int r = off + lane4 * 16 + i;
            __nv_bfloat16 hi, lo;
            split2(sv[i] * inv, hi, lo);
            sPhi[g * APLD + r] = hi;
            sPlo[g * APLD + r] = lo;
        }
    }
    __syncthreads();

    // ---- O = P @ V (banded, compensated): rg = w>>1, col tiles (w&1)*2+j ----
    {
        const int rg   = w >> 1;
        const int half = w & 1;

        wmma::fragment<wmma::accumulator, 16, 16, 16, float> of[2];
        #pragma unroll
        for (int j = 0; j < 2; j++) wmma::fill_fragment(of[j], 0.f);

        #pragma unroll
        for (int tm = 0; tm < 3; tm++) {
            const __nv_bfloat16* Psrc = (tm == 2) ? sPlo : sPhi;
            const __nv_bfloat16* Vsrc = (tm == 1) ? sVlo : sVhi;
            #pragma unroll
            for (int kk = 0; kk < 80; kk += 16) {
                wmma::fragment<wmma::matrix_a, 16, 16, 16, __nv_bfloat16,
                               wmma::row_major> pa;
                wmma::load_matrix_sync(pa, Psrc + rg * 16 * APLD + kk, APLD);
                #pragma unroll
                for (int j = 0; j < 2; j++) {
                    wmma::fragment<wmma::matrix_b, 16, 16, 16, __nv_bfloat16,
                                   wmma::row_major> vb;
                    wmma::load_matrix_sync(vb,
                        Vsrc + (rg * 16 + kk) * AQLD + (half * 2 + j) * 16, AQLD);
                    wmma::mma_sync(of[j], pa, vb, of[j]);
                }
            }
        }
        #pragma unroll
        for (int j = 0; j < 2; j++)
            wmma::store_matrix_sync(sO + rg * 16 * AOLD + (half * 2 + j) * 16,
                                    of[j], AOLD, wmma::mem_row_major);
    }
    __syncthreads();

    // ---- epilogue: split O straight into g_attn2 [hi|hi|lo] layout ----
    for (int i = t; i < 64 * 64; i += 256) {
        int row = i >> 6, c = i & 63;
        float x = sO[row * AOLD + c];
        __nv_bfloat16 hi, lo;
        split2(x, hi, lo);
        __nv_bfloat16* dst = Out2 + (size_t)(b * L_ + l0 + row) * K2_;
        int c2 = (int)headoff + c;
        dst[c2]        = hi;
        dst[512 + c2]  = hi;
        dst[1024 + c2] = lo;
    }
}

// ---------------------------------------------------------------------------
// Launch
// ---------------------------------------------------------------------------
extern "C" void kernel_launch(void* const* d_in, const int* in_sizes, int n_in,
                              void* d_out, int out_size)
{
    const float* query = (const float*)d_in[0];
    const float* key   = (const float*)d_in[1];
    const float* value = (const float*)d_in[2];
    const unsigned char* mask = (const unsigned char*)d_in[3];
    const float* Wq = (const float*)d_in[5];
    const float* Wk = (const float*)d_in[6];
    const float* Wv = (const float*)d_in[7];
    const float* Wo = (const float*)d_in[8];
    float* out = (float*)d_out;

    float *dq, *dk, *dv;
    __nv_bfloat16 *din2, *dat2, *dw2;
    cudaGetSymbolAddress((void**)&dq, g_q);
    cudaGetSymbolAddress((void**)&dk, g_k);
    cudaGetSymbolAddress((void**)&dv, g_v);
    cudaGetSymbolAddress((void**)&din2, g_in2);
    cudaGetSymbolAddress((void**)&dat2, g_attn2);
    cudaGetSymbolAddress((void**)&dw2, g_w2);

    cudaFuncSetAttribute(attn_wmma_kernel,
                         cudaFuncAttributeMaxDynamicSharedMemorySize, SMEM_ATTN);
    cudaFuncSetAttribute(gemm3_kernel,
                         cudaFuncAttributeMaxDynamicSharedMemorySize, GEMM_SMEM);

    // 1) split inputs + weights into compensated bf16 layouts
    split_in_kernel<<<dim3(M_ * D_ / 256, 3), 256>>>(query, key, value);
    split_w_kernel<<<dim3(8, 8, 4), 256>>>(Wq, Wk, Wv, Wo);

    // 2) QKV projections: 3 GEMMs in one tensor-core launch
    const __nv_bfloat16* Aq = din2;
    const __nv_bfloat16* Ak = din2 + (size_t)1 * M_ * K2_;
    const __nv_bfloat16* Av = din2 + (size_t)2 * M_ * K2_;
    const __nv_bfloat16* Bq = dw2;
    const __nv_bfloat16* Bk = dw2 + (size_t)1 * D_ * K2_;
    const __nv_bfloat16* Bv = dw2 + (size_t)2 * D_ * K2_;
    const __nv_bfloat16* Bo = dw2 + (size_t)3 * D_ * K2_;
    gemm3_kernel<<<dim3(D_ / BN, M_ / BM, 3), 256, GEMM_SMEM>>>(
        Aq, Ak, Av, Bq, Bk, Bv, dq, dk, dv);

    // 3) banded local attention (wmma); writes split O directly
    attn_wmma_kernel<<<dim3(16, 8, 4), 256, SMEM_ATTN>>>(dq, dk, dv, mask, dat2);

    // 4) output projection
    gemm3_kernel<<<dim3(D_ / BN, M_ / BM, 1), 256, GEMM_SMEM>>>(
        dat2, dat2, dat2, Bo, Bo, Bo, out, out, out);
}

// round 9
// speedup vs baseline: 2.3275x; 1.0895x over previous
#include <cuda_runtime.h>
#include <cuda_bf16.h>
#include <mma.h>
#include <cstdint>
#include <cstddef>

using namespace nvcuda;

// Problem constants
#define B_   4
#define L_   1024
#define D_   512
#define H_   8
#define EK_  64
#define PADF 32
#define M_   (B_ * L_)    // 4096
#define K2_  1536         // K tripled: [hi|hi|lo] x [hi|lo|hi] compensated layout

// ---------------------------------------------------------------------------
// Scratch (device globals -- no runtime allocation allowed)
// ---------------------------------------------------------------------------
__device__ float g_q[M_ * D_];
__device__ float g_k[M_ * D_];
__device__ float g_v[M_ * D_];
__device__ __align__(256) __nv_bfloat16 g_in2[3ull * M_ * K2_];  // split q,k,v
__device__ __align__(256) __nv_bfloat16 g_attn2[(size_t)M_ * K2_];
__device__ __align__(256) __nv_bfloat16 g_w2[4ull * D_ * K2_];   // split+T weights

// ---------------------------------------------------------------------------
// 2-way split helpers
// ---------------------------------------------------------------------------
__device__ __forceinline__ void split2(float x, __nv_bfloat16& hi,
                                       __nv_bfloat16& lo)
{
    hi = __float2bfloat16(x);
    lo = __float2bfloat16(x - __bfloat162float(hi));
}

__device__ __forceinline__ uint32_t pack2(__nv_bfloat16 a, __nv_bfloat16 b)
{
    __nv_bfloat162 t(a, b);            // .x = a (low half = lower address)
    return *reinterpret_cast<uint32_t*>(&t);
}

// Split a float4 into packed hi (uint2) and lo (uint2).
__device__ __forceinline__ void split4(float4 x, uint2& hi2, uint2& lo2)
{
    __nv_bfloat16 h0, h1, h2, h3, l0, l1, l2, l3;
    split2(x.x, h0, l0); split2(x.y, h1, l1);
    split2(x.z, h2, l2); split2(x.w, h3, l3);
    hi2 = make_uint2(pack2(h0, h1), pack2(h2, h3));
    lo2 = make_uint2(pack2(l0, l1), pack2(l2, l3));
}

__global__ __launch_bounds__(256) void split_in_kernel(
    const float* __restrict__ q, const float* __restrict__ k,
    const float* __restrict__ v)
{
    int i = blockIdx.x * 256 + threadIdx.x;           // over M_*D_/4
    int s = blockIdx.y;
    const float* S = (s == 0) ? q : (s == 1) ? k : v;
    int e = i * 4;
    float4 x = *(const float4*)(S + e);
    uint2 hi2, lo2;
    split4(x, hi2, lo2);
    int r = e >> 9, c = e & 511;
    __nv_bfloat16* dst = g_in2 + (size_t)s * M_ * K2_ + (size_t)r * K2_ + c;
    *(uint2*)(dst)        = hi2;   // pairs with w_hi
    *(uint2*)(dst + 512)  = hi2;   // pairs with w_lo
    *(uint2*)(dst + 1024) = lo2;   // pairs with w_hi
}

// Weights: W[K=512][N=512] row-major -> Wt[n][j]=hi, Wt[n][512+j]=lo, [1024+j]=hi
__global__ __launch_bounds__(256) void split_w_kernel(
    const float* __restrict__ Wq, const float* __restrict__ Wk,
    const float* __restrict__ Wv, const float* __restrict__ Wo)
{
    __shared__ float tile[64][65];
    int z = blockIdx.z;
    const float* W = (z == 0) ? Wq : (z == 1) ? Wk : (z == 2) ? Wv : Wo;
    int j0 = blockIdx.x * 64, n0 = blockIdx.y * 64;
    for (int i = threadIdx.x; i < 4096; i += 256) {
        int r = i >> 6, c = i & 63;
        tile[r][c] = W[(size_t)(j0 + r) * D_ + n0 + c];
    }
    __syncthreads();
    __nv_bfloat16* dst = g_w2 + (size_t)z * D_ * K2_;
    for (int i = threadIdx.x; i < 4096; i += 256) {
        int r = i >> 6, c = i & 63;           // r: local n, c: local j
        float x = tile[c][r];
        __nv_bfloat16 hi, lo;
        split2(x, hi, lo);
        __nv_bfloat16* row = dst + (size_t)(n0 + r) * K2_;
        row[j0 + c]        = hi;
        row[512 + j0 + c]  = lo;
        row[1024 + j0 + c] = hi;
    }
}

// ---------------------------------------------------------------------------
// wmma bf16 GEMM: C[M_,512] = A2[M_,1536] @ Wt[512,1536]^T
// Block tile 128x128, 8 warps, K-chunk 64, 3-stage cp.async pipeline,
// ONE __syncthreads + one wait_group per k-iter (always-commit indexing).
// ---------------------------------------------------------------------------
#define BM 128
#define BN 128
#define BK 64
#define STR 72                       // smem row stride (bf16), 144B
#define NKT (K2_ / BK)               // 24
#define TILE_ELEMS (128 * STR)       // 9216
#define NSTAGE 3
#define GEMM_SMEM (NSTAGE * 2 * TILE_ELEMS * 2)   // 110592 B

__device__ __forceinline__ void cp16(uint32_t dst, const void* src) {
    asm volatile("cp.async.cg.shared.global [%0], [%1], 16;"
                 :: "r"(dst), "l"(src));
}

__device__ __forceinline__ uint32_t smem_u32(const void* p) {
    uint32_t a;
    asm("{ .reg .u64 t; cvta.to.shared.u64 t, %1; cvt.u32.u64 %0, t; }"
        : "=r"(a) : "l"(p));
    return a;
}

// Load one 128x64 bf16 tile (rows K2_-strided) into smem stage.
__device__ __forceinline__ void tile_loads(const __nv_bfloat16* __restrict__ G,
                                           uint32_t sbase, int t)
{
    #pragma unroll
    for (int i = 0; i < 4; i++) {
        int idx = t + i * 256;              // 0..1023 chunks of 16B
        int row = idx >> 3, c = idx & 7;
        cp16(sbase + (uint32_t)(row * (STR * 2) + c * 16),
             G + (size_t)row * K2_ + c * 8);
    }
}

__global__ __launch_bounds__(256, 2) void gemm3_kernel(
    const __nv_bfloat16* __restrict__ A0, const __nv_bfloat16* __restrict__ A1,
    const __nv_bfloat16* __restrict__ A2,
    const __nv_bfloat16* __restrict__ Bw0, const __nv_bfloat16* __restrict__ Bw1,
    const __nv_bfloat16* __restrict__ Bw2,
    float* __restrict__ C0, float* __restrict__ C1, float* __restrict__ C2)
{
    extern __shared__ __align__(256) __nv_bfloat16 gsm[];
    __nv_bfloat16* sA = gsm;                          // [NSTAGE][TILE_ELEMS]
    __nv_bfloat16* sB = gsm + NSTAGE * TILE_ELEMS;    // [NSTAGE][TILE_ELEMS]

    const int z = blockIdx.z;
    const __nv_bfloat16* A  = (z == 0) ? A0  : (z == 1) ? A1  : A2;
    const __nv_bfloat16* Bw = (z == 0) ? Bw0 : (z == 1) ? Bw1 : Bw2;
    float* C                = (z == 0) ? C0  : (z == 1) ? C1  : C2;

    const int t   = threadIdx.x;
    const int wid = t >> 5;
    const int wm  = wid & 1;
    const int wn  = wid >> 1;
    const int m0  = blockIdx.y * BM, n0 = blockIdx.x * BN;

    const __nv_bfloat16* Abase = A  + (size_t)m0 * K2_;
    const __nv_bfloat16* Bbase = Bw + (size_t)n0 * K2_;
    const uint32_t sAb = smem_u32(sA), sBb = smem_u32(sB);
    const uint32_t stage_bytes = TILE_ELEMS * 2;

    wmma::fragment<wmma::accumulator, 16, 16, 16, float> cf[4][2];
    #pragma unroll
    for (int i = 0; i < 4; i++)
        #pragma unroll
        for (int j = 0; j < 2; j++) wmma::fill_fragment(cf[i][j], 0.f);

    // prologue: stages 0,1 (groups g0, g1)
    tile_loads(Abase, sAb, t);
    tile_loads(Bbase, sBb, t);
    asm volatile("cp.async.commit_group;");
    tile_loads(Abase + BK, sAb + stage_bytes, t);
    tile_loads(Bbase + BK, sBb + stage_bytes, t);
    asm volatile("cp.async.commit_group;");

    #pragma unroll 1
    for (int kt = 0; kt < NKT; kt++) {
        // group g_kt done after this wait (<=1 pending = g_{kt+1})
        asm volatile("cp.async.wait_group 1;");
        __syncthreads();     // make all warps' stage-kt copies visible;
                             // also: everyone finished compute of kt-1
        const int sl = (kt + 2) % NSTAGE;   // == (kt-1)%NSTAGE, consumed @kt-1
        if (kt + 2 < NKT) {
            tile_loads(Abase + (kt + 2) * BK, sAb + sl * stage_bytes, t);
            tile_loads(Bbase + (kt + 2) * BK, sBb + sl * stage_bytes, t);
        }
        asm volatile("cp.async.commit_group;");   // always commit: g_{kt+2}

        const int s = kt % NSTAGE;
        const __nv_bfloat16* sa = sA + s * TILE_ELEMS;
        const __nv_bfloat16* sb = sB + s * TILE_ELEMS;
        #pragma unroll
        for (int kk = 0; kk < BK; kk += 16) {
            wmma::fragment<wmma::matrix_a, 16, 16, 16, __nv_bfloat16,
                           wmma::row_major> af[4];
            wmma::fragment<wmma::matrix_b, 16, 16, 16, __nv_bfloat16,
                           wmma::col_major> bf[2];
            #pragma unroll
            for (int i = 0; i < 4; i++)
                wmma::load_matrix_sync(af[i],
                    sa + (wm * 64 + i * 16) * STR + kk, STR);
            #pragma unroll
            for (int j = 0; j < 2; j++)
                wmma::load_matrix_sync(bf[j],
                    sb + (wn * 32 + j * 16) * STR + kk, STR);
            #pragma unroll
            for (int i = 0; i < 4; i++)
                #pragma unroll
                for (int j = 0; j < 2; j++)
                    wmma::mma_sync(cf[i][j], af[i], bf[j], cf[i][j]);
        }
    }

    #pragma unroll
    for (int i = 0; i < 4; i++)
        #pragma unroll
        for (int j = 0; j < 2; j++)
            wmma::store_matrix_sync(
                C + (size_t)(m0 + wm * 64 + i * 16) * D_ + n0 + wn * 32 + j * 16,
                cf[i][j], D_, wmma::mem_row_major);
}

// ---------------------------------------------------------------------------
// wmma banded local attention. Grid (16, 8, 4), 256 threads, 113.7KB smem,
// __launch_bounds__(256,2) -> 2 CTAs/SM. Vectorized load/epilogue phases.
// ---------------------------------------------------------------------------
#define AQLD 72
#define ASLD 84      // fp32 banded S: 80 + 4
#define APLD 88      // bf16 banded P: 80 + 8
#define AOLD 68      // fp32 staged O: 64 + 4

#define AOFF_Q 0                                   // Qhi,Qlo [64][72]
#define AOFF_K (AOFF_Q + 2 * 64 * AQLD * 2)        // 18432: Khi,Klo [128][72]
#define AOFF_V (AOFF_K + 2 * 128 * AQLD * 2)       // 55296: Vhi,Vlo [128][72]
#define AOFF_S (AOFF_V + 2 * 128 * AQLD * 2)       // 92160: S [64][84] fp32
#define SMEM_ATTN (AOFF_S + 64 * ASLD * 4)         // 113664

__global__ __launch_bounds__(256, 2) void attn_wmma_kernel(
    const float* __restrict__ Q, const float* __restrict__ Kp,
    const float* __restrict__ Vp, const unsigned char* __restrict__ mask,
    __nv_bfloat16* __restrict__ Out2)
{
    extern __shared__ __align__(256) char sm[];
    __nv_bfloat16* sQhi = (__nv_bfloat16*)(sm + AOFF_Q);
    __nv_bfloat16* sQlo = sQhi + 64 * AQLD;
    __nv_bfloat16* sKhi = (__nv_bfloat16*)(sm + AOFF_K);
    __nv_bfloat16* sKlo = sKhi + 128 * AQLD;
    __nv_bfloat16* sVhi = (__nv_bfloat16*)(sm + AOFF_V);
    __nv_bfloat16* sVlo = sVhi + 128 * AQLD;
    float*         sS   = (float*)(sm + AOFF_S);
    // P aliases dead Q+K region (needs 22528 B <= 55296 B)
    __nv_bfloat16* sPhi = (__nv_bfloat16*)(sm + AOFF_Q);
    __nv_bfloat16* sPlo = sPhi + 64 * APLD;
    float*         sO   = sS;                      // [64][68], aliases dead S

    const int l0 = blockIdx.x * 64;
    const int h  = blockIdx.y;
    const int b  = blockIdx.z;
    const int t  = threadIdx.x;
    const int w  = t >> 5;

    const size_t headoff = (size_t)h * EK_;
    const float* Qbase = Q  + (size_t)b * L_ * D_ + headoff;
    const float* Kbase = Kp + (size_t)b * L_ * D_ + headoff;
    const float* Vbase = Vp + (size_t)b * L_ * D_ + headoff;

    // ---- load + split Q (64 rows x 16 float4) ----
    for (int i = t; i < 64 * 16; i += 256) {
        int row = i >> 4, c = (i & 15) << 2;
        float4 x = *(const float4*)(Qbase + (size_t)(l0 + row) * D_ + c);
        uint2 hi2, lo2;
        split4(x, hi2, lo2);
        *(uint2*)(sQhi + row * AQLD + c) = hi2;
        *(uint2*)(sQlo + row * AQLD + c) = lo2;
    }
    // ---- load + split K & V windows (128 rows x 16 float4) ----
    for (int i = t; i < 128 * 16; i += 256) {
        int row = i >> 4, c = (i & 15) << 2;
        int gl = l0 - PADF + row;
        bool in = (gl >= 0) && (gl < L_);
        float4 xk = in ? *(const float4*)(Kbase + (size_t)gl * D_ + c)
                       : make_float4(0.f, 0.f, 0.f, 0.f);
        float4 xv = in ? *(const float4*)(Vbase + (size_t)gl * D_ + c)
                       : make_float4(0.f, 0.f, 0.f, 0.f);
        uint2 khi, klo, vhi, vlo;
        split4(xk, khi, klo);
        split4(xv, vhi, vlo);
        *(uint2*)(sKhi + row * AQLD + c) = khi;
        *(uint2*)(sKlo + row * AQLD + c) = klo;
        *(uint2*)(sVhi + row * AQLD + c) = vhi;
        *(uint2*)(sVlo + row * AQLD + c) = vlo;
    }
    __syncthreads();

    // ---- S (banded): row group rg = w>>1, col tiles split 3/2 across halves.
    {
        const int rg   = w >> 1;
        const int half = w & 1;
        const int j0   = half ? 3 : 0;
        const int nj   = half ? 2 : 3;

        wmma::fragment<wmma::accumulator, 16, 16, 16, float> sf[3];
        #pragma unroll
        for (int j = 0; j < 3; j++) wmma::fill_fragment(sf[j], 0.f);

        #pragma unroll
        for (int tm = 0; tm < 3; tm++) {
            const __nv_bfloat16* Qsrc = (tm == 2) ? sQlo : sQhi;
            const __nv_bfloat16* Ksrc = (tm == 1) ? sKlo : sKhi;
            #pragma unroll
            for (int kk = 0; kk < 64; kk += 16) {
                wmma::fragment<wmma::matrix_a, 16, 16, 16, __nv_bfloat16,
                               wmma::row_major> qa;
                wmma::load_matrix_sync(qa, Qsrc + rg * 16 * AQLD + kk, AQLD);
                #pragma unroll
                for (int j = 0; j < 3; j++) {
                    if (j < nj) {
                        wmma::fragment<wmma::matrix_b, 16, 16, 16, __nv_bfloat16,
                                       wmma::col_major> kb;
                        wmma::load_matrix_sync(kb,
                            Ksrc + (rg * 16 + (j0 + j) * 16) * AQLD + kk, AQLD);
                        wmma::mma_sync(sf[j], qa, kb, sf[j]);
                    }
                }
            }
        }
        #pragma unroll
        for (int j = 0; j < 3; j++)
            if (j < nj)
                wmma::store_matrix_sync(sS + rg * 16 * ASLD + (j0 + j) * 16,
                                        sf[j], ASLD, wmma::mem_row_major);
    }
    __syncthreads();

    // ---- softmax per query row; write banded split P ----
    {
        const int g     = t >> 2;      // query row 0..63
        const int lane4 = t & 3;
        const int G     = g >> 4;
        const int off   = g & 15;      // valid rel start; valid r in [off, off+64)
        const int gl0   = l0 - PADF + 16 * G;
        const unsigned char* mrow = mask + (size_t)b * L_;

        float sv[16];
        #pragma unroll
        for (int i = 0; i < 16; i++) {
            int r  = off + lane4 * 16 + i;
            int gl = gl0 + r;
            bool valid = (gl >= 0) && (gl < L_) && (mrow[gl] == 0);
            sv[i] = valid ? sS[g * ASLD + r] : -1e30f;
        }
        float m = sv[0];
        #pragma unroll
        for (int i = 1; i < 16; i++) m = fmaxf(m, sv[i]);
        m = fmaxf(m, __shfl_xor_sync(0xffffffffu, m, 1));
        m = fmaxf(m, __shfl_xor_sync(0xffffffffu, m, 2));
        float sum = 0.f;
        #pragma unroll
        for (int i = 0; i < 16; i++) { sv[i] = __expf(sv[i] - m); sum += sv[i]; }
        sum += __shfl_xor_sync(0xffffffffu, sum, 1);
        sum += __shfl_xor_sync(0xffffffffu, sum, 2);
        float inv = 1.f / sum;

        // zero full 80-wide band first (warp-synchronous, same-warp rows)
        __nv_bfloat16 z0 = __float2bfloat16(0.f);
        #pragma unroll
        for (int i = 0; i < 20; i++) {
            int r = lane4 * 20 + i;
            sPhi[g * APLD + r] = z0;
            sPlo[g * APLD + r] = z0;
        }
        #pragma unroll
        for (int i = 0; i < 16; i++) {
            int r = off + lane4 * 16 + i;
            __nv_bfloat16 hi, lo;
            split2(sv[i] * inv, hi, lo);
            sPhi[g * APLD + r] = hi;
            sPlo[g * APLD + r] = lo;
        }
    }
    __syncthreads();

    // ---- O = P @ V (banded, compensated): rg = w>>1, col tiles (w&1)*2+j ----
    {
        const int rg   = w >> 1;
        const int half = w & 1;

        wmma::fragment<wmma::accumulator, 16, 16, 16, float> of[2];
        #pragma unroll
        for (int j = 0; j < 2; j++) wmma::fill_fragment(of[j], 0.f);

        #pragma unroll
        for (int tm = 0; tm < 3; tm++) {
            const __nv_bfloat16* Psrc = (tm == 2) ? sPlo : sPhi;
            const __nv_bfloat16* Vsrc = (tm == 1) ? sVlo : sVhi;
            #pragma unroll
            for (int kk = 0; kk < 80; kk += 16) {
                wmma::fragment<wmma::matrix_a, 16, 16, 16, __nv_bfloat16,
                               wmma::row_major> pa;
                wmma::load_matrix_sync(pa, Psrc + rg * 16 * APLD + kk, APLD);
                #pragma unroll
                for (int j = 0; j < 2; j++) {
                    wmma::fragment<wmma::matrix_b, 16, 16, 16, __nv_bfloat16,
                                   wmma::row_major> vb;
                    wmma::load_matrix_sync(vb,
                        Vsrc + (rg * 16 + kk) * AQLD + (half * 2 + j) * 16, AQLD);
                    wmma::mma_sync(of[j], pa, vb, of[j]);
                }
            }
        }
        #pragma unroll
        for (int j = 0; j < 2; j++)
            wmma::store_matrix_sync(sO + rg * 16 * AOLD + (half * 2 + j) * 16,
                                    of[j], AOLD, wmma::mem_row_major);
    }
    __syncthreads();

    // ---- epilogue: split O straight into g_attn2 [hi|hi|lo] (vectorized) ----
    for (int i = t; i < 64 * 16; i += 256) {
        int row = i >> 4, c = (i & 15) << 2;
        float4 x = *(const float4*)(sO + row * AOLD + c);
        uint2 hi2, lo2;
        split4(x, hi2, lo2);
        __nv_bfloat16* dst = Out2 + (size_t)(b * L_ + l0 + row) * K2_
                                  + headoff + c;
        *(uint2*)(dst)        = hi2;
        *(uint2*)(dst + 512)  = hi2;
        *(uint2*)(dst + 1024) = lo2;
    }
}

// ---------------------------------------------------------------------------
// Launch
// ---------------------------------------------------------------------------
extern "C" void kernel_launch(void* const* d_in, const int* in_sizes, int n_in,
                              void* d_out, int out_size)
{
    const float* query = (const float*)d_in[0];
    const float* key   = (const float*)d_in[1];
    const float* value = (const float*)d_in[2];
    const unsigned char* mask = (const unsigned char*)d_in[3];
    const float* Wq = (const float*)d_in[5];
    const float* Wk = (const float*)d_in[6];
    const float* Wv = (const float*)d_in[7];
    const float* Wo = (const float*)d_in[8];
    float* out = (float*)d_out;

    float *dq, *dk, *dv;
    __nv_bfloat16 *din2, *dat2, *dw2;
    cudaGetSymbolAddress((void**)&dq, g_q);
    cudaGetSymbolAddress((void**)&dk, g_k);
    cudaGetSymbolAddress((void**)&dv, g_v);
    cudaGetSymbolAddress((void**)&din2, g_in2);
    cudaGetSymbolAddress((void**)&dat2, g_attn2);
    cudaGetSymbolAddress((void**)&dw2, g_w2);

    cudaFuncSetAttribute(attn_wmma_kernel,
                         cudaFuncAttributeMaxDynamicSharedMemorySize, SMEM_ATTN);
    cudaFuncSetAttribute(gemm3_kernel,
                         cudaFuncAttributeMaxDynamicSharedMemorySize, GEMM_SMEM);

    // 1) split inputs + weights into compensated bf16 layouts
    split_in_kernel<<<dim3(M_ * D_ / 1024, 3), 256>>>(query, key, value);
    split_w_kernel<<<dim3(8, 8, 4), 256>>>(Wq, Wk, Wv, Wo);

    // 2) QKV projections: 3 GEMMs in one tensor-core launch
    const __nv_bfloat16* Aq = din2;
    const __nv_bfloat16* Ak = din2 + (size_t)1 * M_ * K2_;
    const __nv_bfloat16* Av = din2 + (size_t)2 * M_ * K2_;
    const __nv_bfloat16* Bq = dw2;
    const __nv_bfloat16* Bk = dw2 + (size_t)1 * D_ * K2_;
    const __nv_bfloat16* Bv = dw2 + (size_t)2 * D_ * K2_;
    const __nv_bfloat16* Bo = dw2 + (size_t)3 * D_ * K2_;
    gemm3_kernel<<<dim3(D_ / BN, M_ / BM, 3), 256, GEMM_SMEM>>>(
        Aq, Ak, Av, Bq, Bk, Bv, dq, dk, dv);

    // 3) banded local attention (wmma); writes split O directly
    attn_wmma_kernel<<<dim3(16, 8, 4), 256, SMEM_ATTN>>>(dq, dk, dv, mask, dat2);

    // 4) output projection
    gemm3_kernel<<<dim3(D_ / BN, M_ / BM, 1), 256, GEMM_SMEM>>>(
        dat2, dat2, dat2, Bo, Bo, Bo, out, out, out);
}